// round 1
// baseline (speedup 1.0000x reference)
#include <cuda_runtime.h>
#include <math.h>

// ---------------- problem constants ----------------
constexpr int NE  = 20000;   // NUM_E
constexpr int H   = 200;
constexpr int EE  = 200000;  // E
constexpr int NB  = 512;     // BATCH
constexpr int TD  = 48;
constexpr int HDh = 24;      // TD/2

// ---------------- device scratch (no allocs allowed) ----------------
__device__ float g_prev[NE * H];
__device__ float g_hA[NE * H];
__device__ float g_hB[NE * H];
__device__ float g_pre[NE * H];
__device__ float g_relS[NE * H];
__device__ float g_gi[NE * 3 * H];
__device__ float g_gh[NE * 3 * H];
__device__ float g_reln[400 * H];
__device__ int   g_deg[NE];
__device__ int   g_rowptr[NE + 1];
__device__ int   g_cursor[NE];
__device__ int   g_esrc[EE];
__device__ int   g_erel[EE];
__device__ float g_biasP[3 * H];
__device__ float g_biasN[3 * H];
__device__ float g_sbuf[3][NB * H];
__device__ float g_cat[NB * 648];
__device__ float g_abuf[NB * H];
__device__ float g_atts[NB * 3];
__device__ float g_cat600[NB * 600];
__device__ float g_q[NB * H];

// ---------------- generic SGEMM ----------------
// C[M,N] = A[M,K] @ op(B) (+ A2[M,K] @ op(B2) if DUAL) (+ bias[n] if BIAS), relu if RELU
// TRB: B is stored [N, ldb] and used transposed: B^T(k,n) = B[n*ldb + k]
template <bool TRB, bool DUAL, bool RELU, bool BIAS>
__global__ void sgemm_kernel(const float* __restrict__ A, int lda,
                             const float* __restrict__ B, int ldb,
                             const float* __restrict__ A2,
                             const float* __restrict__ B2,
                             const float* __restrict__ bias,
                             float* __restrict__ C, int ldc,
                             int M, int N, int K) {
    constexpr int BM = 64, BN = 64, BK = 16;
    __shared__ float As[BK][BM];
    __shared__ float Bs[BK][BN];
    const int bm = blockIdx.y * BM;
    const int bn = blockIdx.x * BN;
    const int t  = threadIdx.x;       // 256 threads
    const int tx = t & 15, ty = t >> 4;
    float acc[4][4] = {};

    const int nPass = DUAL ? 2 : 1;
    for (int pass = 0; pass < nPass; pass++) {
        const float* Ap = pass ? A2 : A;
        const float* Bp = pass ? B2 : B;
        for (int k0 = 0; k0 < K; k0 += BK) {
#pragma unroll
            for (int r = 0; r < 4; r++) {
                int idx = t + r * 256;
                int m = idx >> 4, kk = idx & 15;
                int gm = bm + m, gk = k0 + kk;
                As[kk][m] = (gm < M && gk < K) ? Ap[gm * lda + gk] : 0.f;
            }
            if (TRB) {
#pragma unroll
                for (int r = 0; r < 4; r++) {
                    int idx = t + r * 256;
                    int n = idx >> 4, kk = idx & 15;
                    int gn = bn + n, gk = k0 + kk;
                    Bs[kk][n] = (gn < N && gk < K) ? Bp[gn * ldb + gk] : 0.f;
                }
            } else {
#pragma unroll
                for (int r = 0; r < 4; r++) {
                    int idx = t + r * 256;
                    int kk = idx >> 6, n = idx & 63;
                    int gn = bn + n, gk = k0 + kk;
                    Bs[kk][n] = (gn < N && gk < K) ? Bp[gk * ldb + gn] : 0.f;
                }
            }
            __syncthreads();
#pragma unroll
            for (int kk = 0; kk < BK; kk++) {
                float a[4], b[4];
#pragma unroll
                for (int i = 0; i < 4; i++) a[i] = As[kk][ty * 4 + i];
#pragma unroll
                for (int j = 0; j < 4; j++) b[j] = Bs[kk][tx * 4 + j];
#pragma unroll
                for (int i = 0; i < 4; i++)
#pragma unroll
                    for (int j = 0; j < 4; j++) acc[i][j] += a[i] * b[j];
            }
            __syncthreads();
        }
    }
#pragma unroll
    for (int i = 0; i < 4; i++) {
        int gm = bm + ty * 4 + i;
        if (gm >= M) continue;
#pragma unroll
        for (int j = 0; j < 4; j++) {
            int gn = bn + tx * 4 + j;
            if (gn >= N) continue;
            float v = acc[i][j];
            if (BIAS) v += bias[gn];
            if (RELU) v = fmaxf(v, 0.f);
            C[gm * ldc + gn] = v;
        }
    }
}

// ---------------- row L2 normalize (warp per row) ----------------
__global__ void l2n_kernel(const float* __restrict__ in, float* __restrict__ outp, int rows) {
    int r = blockIdx.x * blockDim.y + threadIdx.y;
    if (r >= rows) return;
    int lane = threadIdx.x;
    float s = 0.f;
    for (int c = lane; c < H; c += 32) { float v = in[r * H + c]; s += v * v; }
#pragma unroll
    for (int off = 16; off; off >>= 1) s += __shfl_xor_sync(0xffffffffu, s, off);
    float sc = 1.f / fmaxf(sqrtf(s), 1e-12f);
    for (int c = lane; c < H; c += 32) outp[r * H + c] = in[r * H + c] * sc;
}

// ---------------- CSR build ----------------
__global__ void count_kernel(const int* __restrict__ dsti) {
    int e = blockIdx.x * blockDim.x + threadIdx.x;
    if (e < EE) atomicAdd(&g_deg[dsti[e]], 1);
}

__global__ void scan_kernel() {
    __shared__ int s[1024];
    int t = threadIdx.x;
    int start = t * 20;
    int end = min(start + 20, NE);
    int local = 0;
    for (int i = start; i < end; i++) local += g_deg[i];
    s[t] = local;
    __syncthreads();
    for (int off = 1; off < 1024; off <<= 1) {
        int v = (t >= off) ? s[t - off] : 0;
        __syncthreads();
        s[t] += v;
        __syncthreads();
    }
    int run = s[t] - local;
    for (int i = start; i < end; i++) {
        g_rowptr[i] = run;
        g_cursor[i] = run;
        run += g_deg[i];
    }
    if (t == 1023) g_rowptr[NE] = run;
}

__global__ void fill_kernel(const int* __restrict__ srci, const int* __restrict__ dsti,
                            const int* __restrict__ eti) {
    int e = blockIdx.x * blockDim.x + threadIdx.x;
    if (e < EE) {
        int p = atomicAdd(&g_cursor[dsti[e]], 1);
        g_esrc[p] = srci[e];
        g_erel[p] = eti[e];
    }
}

// ---------------- aggregation passes (CSR gather, no float atomics) ----------------
// h = l2n(where(deg>0, segsum(prev[src])/max(deg,1), 0));  relS = segsum(rel_n[etype])
__global__ void gather1_kernel() {
    int n = blockIdx.x, c = threadIdx.x;
    int b0 = g_rowptr[n], e0 = g_rowptr[n + 1];
    float s1 = 0.f, s2 = 0.f;
    if (c < H) {
        for (int i = b0; i < e0; i++) {
            s1 += g_prev[g_esrc[i] * H + c];
            s2 += g_reln[g_erel[i] * H + c];
        }
    }
    float inv = 1.f / fmaxf((float)(e0 - b0), 1.f);
    float v = s1 * inv;
    __shared__ float red[256];
    red[threadIdx.x] = (c < H) ? v * v : 0.f;
    __syncthreads();
    for (int off = 128; off; off >>= 1) {
        if (threadIdx.x < off) red[threadIdx.x] += red[threadIdx.x + off];
        __syncthreads();
    }
    float sc = 1.f / fmaxf(sqrtf(red[0]), 1e-12f);
    if (c < H) {
        g_hA[n * H + c] = v * sc;
        g_relS[n * H + c] = s2;
    }
}

// pre = (segsum(h[src]) + relS) * inv   (matmul with Wn done by SGEMM afterwards)
__global__ void gather2_kernel(const float* __restrict__ hsrc) {
    int n = blockIdx.x, c = threadIdx.x;
    if (c >= H) return;
    int b0 = g_rowptr[n], e0 = g_rowptr[n + 1];
    float s = 0.f;
    for (int i = b0; i < e0; i++) s += hsrc[g_esrc[i] * H + c];
    float inv = 1.f / fmaxf((float)(e0 - b0), 1.f);
    g_pre[n * H + c] = (s + g_relS[n * H + c]) * inv;
}

// ---------------- time-encoding bias (2-valued): bias = b_ih + W_ih[:,200:248] @ te ----------------
__global__ void tebias_kernel(const float* __restrict__ W_ih, const float* __restrict__ b_ih,
                              const float* __restrict__ af, const float* __restrict__ ap,
                              const float* __restrict__ cf, const float* __restrict__ cp,
                              float tpos) {
    int j = blockIdx.x * blockDim.x + threadIdx.x;
    if (j >= 3 * H) return;
    float sp = b_ih[j], sn = b_ih[j];
    for (int d = 0; d < TD; d++) {
        float tep, ten;
        if (d < HDh) {
            tep = tanhf((tpos + 1.f) * af[d] + ap[d]);
            ten = tanhf(101.f * af[d] + ap[d]);
        } else {
            tep = cosf(tpos * cf[d - HDh] + cp[d - HDh]);
            ten = cosf(100.f * cf[d - HDh] + cp[d - HDh]);
        }
        float w = W_ih[j * 248 + 200 + d];
        sp += w * tep;
        sn += w * ten;
    }
    g_biasP[j] = sp;
    g_biasN[j] = sn;
}

// ---------------- GRU update + l2n (block per node) ----------------
__global__ void gru_kernel(const float* __restrict__ b_hh) {
    int n = blockIdx.x, c = threadIdx.x;
    const float* bp = (g_deg[n] > 0) ? g_biasP : g_biasN;
    float v = 0.f;
    if (c < H) {
        float ir = g_gi[n * 600 + c]       + bp[c];
        float iz = g_gi[n * 600 + 200 + c] + bp[200 + c];
        float in_ = g_gi[n * 600 + 400 + c] + bp[400 + c];
        float hr = g_gh[n * 600 + c]       + b_hh[c];
        float hz = g_gh[n * 600 + 200 + c] + b_hh[200 + c];
        float hn = g_gh[n * 600 + 400 + c] + b_hh[400 + c];
        float rg = 1.f / (1.f + expf(-(ir + hr)));
        float zg = 1.f / (1.f + expf(-(iz + hz)));
        float ng = tanhf(in_ + rg * hn);
        v = (1.f - zg) * ng + zg * g_prev[n * H + c];
    }
    __shared__ float red[256];
    red[threadIdx.x] = v * v;
    __syncthreads();
    for (int off = 128; off; off >>= 1) {
        if (threadIdx.x < off) red[threadIdx.x] += red[threadIdx.x + off];
        __syncthreads();
    }
    float sc = 1.f / fmaxf(sqrtf(red[0]), 1e-12f);
    if (c < H) g_prev[n * H + c] = v * sc;
}

// ---------------- phase 2: history summaries ----------------
__global__ void tmp_kernel(const int* __restrict__ his_idx, const int* __restrict__ his_len) {
    int b = blockIdx.x, k = blockIdx.y, c = threadIdx.x;
    int ln = his_len[b * 3 + k];
    float s = 0.f;
    if (c < H) {
        for (int l = 0; l < ln; l++) {
            int idx = his_idx[(b * 3 + k) * 32 + l];
            s += g_prev[idx * H + c];
        }
    }
    float v = s / fmaxf((float)ln, 1.f);
    __shared__ float red[256];
    red[threadIdx.x] = (c < H) ? v * v : 0.f;
    __syncthreads();
    for (int off = 128; off; off >>= 1) {
        if (threadIdx.x < off) red[threadIdx.x] += red[threadIdx.x + off];
        __syncthreads();
    }
    float sc = 1.f / fmaxf(sqrtf(red[0]), 1e-12f);
    if (c < H) g_sbuf[k][b * H + c] = v * sc;
}

__global__ void cat_kernel(int k, float timk, const int* __restrict__ data,
                           const int* __restrict__ his_len,
                           const float* __restrict__ af, const float* __restrict__ ap,
                           const float* __restrict__ cf, const float* __restrict__ cp) {
    int b = blockIdx.x, c = threadIdx.x;
    int si = data[b * 4 + 0], ri = data[b * 4 + 1];
    if (c < H) {
        g_cat[b * 648 + c]       = g_prev[si * H + c];
        g_cat[b * 648 + 200 + c] = g_reln[ri * H + c];
        g_cat[b * 648 + 400 + c] = g_sbuf[k][b * H + c];
    }
    if (c < TD) {
        int ln = his_len[b * 3 + k];
        float t = (ln > 0) ? timk : 100.f;
        float v = (c < HDh) ? tanhf((t + 1.f) * af[c] + ap[c])
                            : cosf(t * cf[c - HDh] + cp[c - HDh]);
        g_cat[b * 648 + 600 + c] = v;
    }
}

__global__ void atts_kernel(int k, const float* __restrict__ Wc_w, const float* __restrict__ Wc_b) {
    int warp = (blockIdx.x * blockDim.x + threadIdx.x) >> 5;
    int lane = threadIdx.x & 31;
    if (warp >= NB) return;
    float s = 0.f;
    for (int c = lane; c < H; c += 32) s += g_abuf[warp * H + c] * Wc_w[c];
#pragma unroll
    for (int off = 16; off; off >>= 1) s += __shfl_xor_sync(0xffffffffu, s, off);
    if (lane == 0) g_atts[warp * 3 + k] = s + Wc_b[0];
}

__global__ void combine_kernel(const int* __restrict__ data) {
    int b = blockIdx.x, c = threadIdx.x;
    float a0 = g_atts[b * 3 + 0], a1 = g_atts[b * 3 + 1], a2 = g_atts[b * 3 + 2];
    float m = fmaxf(a0, fmaxf(a1, a2));
    float e0 = expf(a0 - m), e1 = expf(a1 - m), e2 = expf(a2 - m);
    float inv = 1.f / (e0 + e1 + e2);
    if (c < H) {
        int si = data[b * 4 + 0], ri = data[b * 4 + 1];
        float o2 = (e0 * g_sbuf[0][b * H + c] + e1 * g_sbuf[1][b * H + c] +
                    e2 * g_sbuf[2][b * H + c]) * inv;
        g_cat600[b * 600 + c]       = g_prev[si * H + c];
        g_cat600[b * 600 + 200 + c] = g_reln[ri * H + c];
        g_cat600[b * 600 + 400 + c] = o2;
    }
}

// ---------------- host orchestration ----------------
static inline dim3 gemm_grid(int N, int M) { return dim3((N + 63) / 64, (M + 63) / 64); }

extern "C" void kernel_launch(void* const* d_in, const int* in_sizes, int n_in,
                              void* d_out, int out_size) {
    (void)in_sizes; (void)n_in; (void)out_size;
    const int*   src    = (const int*)d_in[0];
    const int*   dst    = (const int*)d_in[1];
    const int*   etype  = (const int*)d_in[2];
    const int*   data   = (const int*)d_in[3];
    const int*   hisidx = (const int*)d_in[4];
    const int*   hislen = (const int*)d_in[5];
    const float* ent    = (const float*)d_in[6];
    const float* loopw  = (const float*)d_in[7];
    const float* rel    = (const float*)d_in[8];
    const float* absf   = (const float*)d_in[9];
    const float* absp   = (const float*)d_in[10];
    const float* cosfr  = (const float*)d_in[11];
    const float* cosph  = (const float*)d_in[12];
    const float* Wn     = (const float*)d_in[13];
    const float* Wsm    = (const float*)d_in[14];
    const float* W_ih   = (const float*)d_in[15];
    const float* W_hh   = (const float*)d_in[16];
    const float* b_ih   = (const float*)d_in[17];
    const float* b_hh   = (const float*)d_in[18];
    const float* Wb_w   = (const float*)d_in[19];
    const float* Wb_b   = (const float*)d_in[20];
    const float* Wc_w   = (const float*)d_in[21];
    const float* Wc_b   = (const float*)d_in[22];
    const float* Wd_w   = (const float*)d_in[23];
    const float* Wd_b   = (const float*)d_in[24];
    float* outp = (float*)d_out;

    float *prev, *hA, *hB, *pre, *gi, *gh, *reln, *cat, *cat600, *abuf, *qb;
    int* degp;
    void* p;
    cudaGetSymbolAddress(&p, g_prev);   prev   = (float*)p;
    cudaGetSymbolAddress(&p, g_hA);     hA     = (float*)p;
    cudaGetSymbolAddress(&p, g_hB);     hB     = (float*)p;
    cudaGetSymbolAddress(&p, g_pre);    pre    = (float*)p;
    cudaGetSymbolAddress(&p, g_gi);     gi     = (float*)p;
    cudaGetSymbolAddress(&p, g_gh);     gh     = (float*)p;
    cudaGetSymbolAddress(&p, g_reln);   reln   = (float*)p;
    cudaGetSymbolAddress(&p, g_cat);    cat    = (float*)p;
    cudaGetSymbolAddress(&p, g_cat600); cat600 = (float*)p;
    cudaGetSymbolAddress(&p, g_abuf);   abuf   = (float*)p;
    cudaGetSymbolAddress(&p, g_q);      qb     = (float*)p;
    cudaGetSymbolAddress(&p, g_deg);    degp   = (int*)p;

    const dim3 l2nBlk(32, 8);

    // rel_n = l2n(rel)
    l2n_kernel<<<(400 + 7) / 8, l2nBlk>>>(rel, reln, 400);
    // prev = l2n(ent @ loop_weight)
    sgemm_kernel<false, false, false, false><<<gemm_grid(H, NE), 256>>>(
        ent, H, loopw, H, nullptr, nullptr, nullptr, pre, H, NE, H, H);
    l2n_kernel<<<(NE + 7) / 8, l2nBlk>>>(pre, prev, NE);

    for (int i = 0; i < 3; i++) {
        // CSR build for snapshot i
        cudaMemsetAsync(degp, 0, NE * sizeof(int), 0);
        count_kernel<<<(EE + 511) / 512, 512>>>(dst + i * EE);
        scan_kernel<<<1, 1024>>>();
        fill_kernel<<<(EE + 511) / 512, 512>>>(src + i * EE, dst + i * EE, etype + i * EE);
        // h init + rel segment sums
        gather1_kernel<<<NE, 256>>>();
        // time-encoding GRU biases for this step (tim = 2 - i for active, 100 otherwise)
        tebias_kernel<<<3, 256>>>(W_ih, b_ih, absf, absp, cosfr, cosph, (float)(2 - i));
        // layer 0: hB = relu(pre @ Wn[0] + hA @ Ws[0])
        gather2_kernel<<<NE, 256>>>(hA);
        sgemm_kernel<false, true, true, false><<<gemm_grid(H, NE), 256>>>(
            pre, H, Wn, H, hA, Wsm, nullptr, hB, H, NE, H, H);
        // layer 1: hA = relu(pre @ Wn[1] + hB @ Ws[1])
        gather2_kernel<<<NE, 256>>>(hB);
        sgemm_kernel<false, true, true, false><<<gemm_grid(H, NE), 256>>>(
            pre, H, Wn + H * H, H, hB, Wsm + H * H, nullptr, hA, H, NE, H, H);
        // h = l2n(h)
        l2n_kernel<<<(NE + 7) / 8, l2nBlk>>>(hA, hA, NE);
        // GRU gates: gi = h @ W_ih[:, :200]^T ; gh = prev @ W_hh^T
        sgemm_kernel<true, false, false, false><<<gemm_grid(3 * H, NE), 256>>>(
            hA, H, W_ih, 248, nullptr, nullptr, nullptr, gi, 3 * H, NE, 3 * H, H);
        sgemm_kernel<true, false, false, false><<<gemm_grid(3 * H, NE), 256>>>(
            prev, H, W_hh, H, nullptr, nullptr, nullptr, gh, 3 * H, NE, 3 * H, H);
        gru_kernel<<<NE, 256>>>(b_hh);
    }

    // ---- phase 2: batch attention over histories ----
    tmp_kernel<<<dim3(NB, 3), 256>>>(hisidx, hislen);
    for (int k = 0; k < 3; k++) {
        cat_kernel<<<NB, 256>>>(k, (float)(2 - k), data, hislen, absf, absp, cosfr, cosph);
        sgemm_kernel<true, false, true, true><<<gemm_grid(H, NB), 256>>>(
            cat, 648, Wb_w, 648, nullptr, nullptr, Wb_b, abuf, H, NB, H, 648);
        atts_kernel<<<64, 256>>>(k, Wc_w, Wc_b);
    }
    combine_kernel<<<NB, 256>>>(data);
    sgemm_kernel<true, false, true, true><<<gemm_grid(H, NB), 256>>>(
        cat600, 600, Wd_w, 600, nullptr, nullptr, Wd_b, qb, H, NB, H, 600);
    // result = q @ out^T   (out == prev)
    sgemm_kernel<true, false, false, false><<<gemm_grid(NE, NB), 256>>>(
        qb, H, prev, H, nullptr, nullptr, nullptr, outp, NE, NB, NE, H);
}

// round 6
// speedup vs baseline: 1.5145x; 1.5145x over previous
#include <cuda_runtime.h>
#include <math.h>

// ---------------- problem constants ----------------
constexpr int NE  = 20000;   // NUM_E
constexpr int H   = 200;
constexpr int EE  = 200000;  // E
constexpr int NB  = 512;     // BATCH
constexpr int TD  = 48;
constexpr int HDh = 24;      // TD/2

// ---------------- device scratch (no allocs allowed) ----------------
__device__ float g_prev[NE * H];
__device__ float g_hA[NE * H];
__device__ float g_hB[NE * H];
__device__ float g_pre[NE * H];
__device__ float g_relS[NE * H];
__device__ float g_gi[NE * 3 * H];
__device__ float g_gh[NE * 3 * H];
__device__ float g_reln[400 * H];
__device__ int   g_deg[NE];
__device__ int   g_rowptr[NE + 1];
__device__ int   g_cursor[NE];
__device__ int   g_esrc[EE];
__device__ int   g_erel[EE];
__device__ float g_biasP[3 * H];
__device__ float g_biasN[3 * H];
__device__ float g_sbuf[3][NB * H];
__device__ float g_cat[NB * 648];
__device__ float g_abuf[NB * H];
__device__ float g_atts[NB * 3];
__device__ float g_cat600[NB * 600];
__device__ float g_q[NB * H];

// ---------------- high-throughput SGEMM ----------------
// C[M,N] = A[M,K] @ op(B) (+ A2 @ op(B2) if DUAL) (+ bias if BIAS), relu if RELU
// TRB: B stored [N, ldb], used transposed.
// Requirements (all satisfied by our shapes): K % 8 == 0; lda, ldb, ldc, N all
// multiples of 4 (so float4 loads/stores are 16B aligned).
template <bool TRB, bool DUAL, bool RELU, bool BIAS>
__global__ void __launch_bounds__(256, 2) sgemm_kernel(
    const float* __restrict__ A, int lda,
    const float* __restrict__ B, int ldb,
    const float* __restrict__ A2, const float* __restrict__ B2,
    const float* __restrict__ bias,
    float* __restrict__ C, int ldc, int M, int N, int K) {
    constexpr int BM = 128, BN = 64, BK = 8;
    __shared__ float As[2][BK][BM];
    __shared__ float Bs[2][BK][BN];
    const int bm = blockIdx.y * BM;
    const int bn = blockIdx.x * BN;
    const int t  = threadIdx.x;           // 256 threads
    const int tx = t & 15, ty = t >> 4;   // 16 x 16 thread grid

    // A staging: 128 rows x 8 k = 256 float4; thread -> (row, kpart)
    const int arow = t >> 1;
    const int akp  = (t & 1) * 4;
    // B staging (first 128 threads): 8 x 64 = 128 float4
    const int bkk = t >> 4;          // non-TRB: k row (0..7) for t<128
    const int bnp = (t & 15) * 4;    // non-TRB: col group
    const int brow = t >> 1;         // TRB: n (0..63) for t<128
    const int bkp  = (t & 1) * 4;    // TRB: k part

    const int ksteps = K / BK;
    const int nsteps = (DUAL ? 2 : 1) * ksteps;

    float acc[8][4] = {};
    float4 aReg = make_float4(0.f, 0.f, 0.f, 0.f);
    float4 bReg = make_float4(0.f, 0.f, 0.f, 0.f);

    auto load_step = [&](int s) {
        int pass = DUAL ? (s >= ksteps ? 1 : 0) : 0;
        int k0 = (s - pass * ksteps) * BK;
        const float* Ap = pass ? A2 : A;
        const float* Bp = pass ? B2 : B;
        int gm = bm + arow;
        aReg = (gm < M) ? *(const float4*)(Ap + (size_t)gm * lda + k0 + akp)
                        : make_float4(0.f, 0.f, 0.f, 0.f);
        if (t < 128) {
            if (TRB) {
                int gn = bn + brow;
                bReg = (gn < N) ? *(const float4*)(Bp + (size_t)gn * ldb + k0 + bkp)
                                : make_float4(0.f, 0.f, 0.f, 0.f);
            } else {
                int gn = bn + bnp;   // gn % 4 == 0, N % 4 == 0 -> gn<N implies gn+3<N
                bReg = (gn < N) ? *(const float4*)(Bp + (size_t)(k0 + bkk) * ldb + gn)
                                : make_float4(0.f, 0.f, 0.f, 0.f);
            }
        }
    };

    auto store_smem = [&](int buf) {
        As[buf][akp + 0][arow] = aReg.x;
        As[buf][akp + 1][arow] = aReg.y;
        As[buf][akp + 2][arow] = aReg.z;
        As[buf][akp + 3][arow] = aReg.w;
        if (t < 128) {
            if (TRB) {
                Bs[buf][bkp + 0][brow] = bReg.x;
                Bs[buf][bkp + 1][brow] = bReg.y;
                Bs[buf][bkp + 2][brow] = bReg.z;
                Bs[buf][bkp + 3][brow] = bReg.w;
            } else {
                *(float4*)&Bs[buf][bkk][bnp] = bReg;
            }
        }
    };

    auto compute = [&](int buf) {
#pragma unroll
        for (int kk = 0; kk < BK; kk++) {
            float4 a0 = *(const float4*)&As[buf][kk][ty * 8];
            float4 a1 = *(const float4*)&As[buf][kk][ty * 8 + 4];
            float4 bv = *(const float4*)&Bs[buf][kk][tx * 4];
            float a[8] = {a0.x, a0.y, a0.z, a0.w, a1.x, a1.y, a1.z, a1.w};
            float b[4] = {bv.x, bv.y, bv.z, bv.w};
#pragma unroll
            for (int i = 0; i < 8; i++)
#pragma unroll
                for (int j = 0; j < 4; j++) acc[i][j] += a[i] * b[j];
        }
    };

    load_step(0);
    store_smem(0);
    __syncthreads();
    int buf = 0;
    for (int s = 1; s < nsteps; s++) {
        load_step(s);
        compute(buf);
        store_smem(buf ^ 1);
        __syncthreads();
        buf ^= 1;
    }
    compute(buf);

    // epilogue: vectorized float4 stores (N % 4 == 0, ldc*4 multiple of 16)
    const int gn = bn + tx * 4;
    if (gn < N) {
        float4 bias4;
        if (BIAS) bias4 = *(const float4*)(bias + gn);
#pragma unroll
        for (int i = 0; i < 8; i++) {
            int gm = bm + ty * 8 + i;
            if (gm >= M) continue;
            float4 v = make_float4(acc[i][0], acc[i][1], acc[i][2], acc[i][3]);
            if (BIAS) { v.x += bias4.x; v.y += bias4.y; v.z += bias4.z; v.w += bias4.w; }
            if (RELU) {
                v.x = fmaxf(v.x, 0.f); v.y = fmaxf(v.y, 0.f);
                v.z = fmaxf(v.z, 0.f); v.w = fmaxf(v.w, 0.f);
            }
            *(float4*)(C + (size_t)gm * ldc + gn) = v;
        }
    }
}

// ---------------- row L2 normalize (warp per row) ----------------
__global__ void l2n_kernel(const float* __restrict__ in, float* __restrict__ outp, int rows) {
    int r = blockIdx.x * blockDim.y + threadIdx.y;
    if (r >= rows) return;
    int lane = threadIdx.x;
    float s = 0.f;
    for (int c = lane; c < H; c += 32) { float v = in[r * H + c]; s += v * v; }
#pragma unroll
    for (int off = 16; off; off >>= 1) s += __shfl_xor_sync(0xffffffffu, s, off);
    float sc = 1.f / fmaxf(sqrtf(s), 1e-12f);
    for (int c = lane; c < H; c += 32) outp[r * H + c] = in[r * H + c] * sc;
}

// ---------------- CSR build ----------------
__global__ void count_kernel(const int* __restrict__ dsti) {
    int e = blockIdx.x * blockDim.x + threadIdx.x;
    if (e < EE) atomicAdd(&g_deg[dsti[e]], 1);
}

__global__ void scan_kernel() {
    __shared__ int s[1024];
    int t = threadIdx.x;
    int start = t * 20;
    int end = min(start + 20, NE);
    int local = 0;
    for (int i = start; i < end; i++) local += g_deg[i];
    s[t] = local;
    __syncthreads();
    for (int off = 1; off < 1024; off <<= 1) {
        int v = (t >= off) ? s[t - off] : 0;
        __syncthreads();
        s[t] += v;
        __syncthreads();
    }
    int run = s[t] - local;
    for (int i = start; i < end; i++) {
        g_rowptr[i] = run;
        g_cursor[i] = run;
        run += g_deg[i];
    }
    if (t == 1023) g_rowptr[NE] = run;
}

__global__ void fill_kernel(const int* __restrict__ srci, const int* __restrict__ dsti,
                            const int* __restrict__ eti) {
    int e = blockIdx.x * blockDim.x + threadIdx.x;
    if (e < EE) {
        int p = atomicAdd(&g_cursor[dsti[e]], 1);
        g_esrc[p] = srci[e];
        g_erel[p] = eti[e];
    }
}

// ---------------- aggregation passes (CSR gather, no float atomics) ----------------
__global__ void gather1_kernel() {
    int n = blockIdx.x, c = threadIdx.x;
    int b0 = g_rowptr[n], e0 = g_rowptr[n + 1];
    float s1 = 0.f, s2 = 0.f;
    if (c < H) {
        for (int i = b0; i < e0; i++) {
            s1 += g_prev[g_esrc[i] * H + c];
            s2 += g_reln[g_erel[i] * H + c];
        }
    }
    float inv = 1.f / fmaxf((float)(e0 - b0), 1.f);
    float v = s1 * inv;
    __shared__ float red[256];
    red[threadIdx.x] = (c < H) ? v * v : 0.f;
    __syncthreads();
    for (int off = 128; off; off >>= 1) {
        if (threadIdx.x < off) red[threadIdx.x] += red[threadIdx.x + off];
        __syncthreads();
    }
    float sc = 1.f / fmaxf(sqrtf(red[0]), 1e-12f);
    if (c < H) {
        g_hA[n * H + c] = v * sc;
        g_relS[n * H + c] = s2;
    }
}

__global__ void gather2_kernel(const float* __restrict__ hsrc) {
    int n = blockIdx.x, c = threadIdx.x;
    if (c >= H) return;
    int b0 = g_rowptr[n], e0 = g_rowptr[n + 1];
    float s = 0.f;
    for (int i = b0; i < e0; i++) s += hsrc[g_esrc[i] * H + c];
    float inv = 1.f / fmaxf((float)(e0 - b0), 1.f);
    g_pre[n * H + c] = (s + g_relS[n * H + c]) * inv;
}

// ---------------- time-encoding bias ----------------
__global__ void tebias_kernel(const float* __restrict__ W_ih, const float* __restrict__ b_ih,
                              const float* __restrict__ af, const float* __restrict__ ap,
                              const float* __restrict__ cf, const float* __restrict__ cp,
                              float tpos) {
    int j = blockIdx.x * blockDim.x + threadIdx.x;
    if (j >= 3 * H) return;
    float sp = b_ih[j], sn = b_ih[j];
    for (int d = 0; d < TD; d++) {
        float tep, ten;
        if (d < HDh) {
            tep = tanhf((tpos + 1.f) * af[d] + ap[d]);
            ten = tanhf(101.f * af[d] + ap[d]);
        } else {
            tep = cosf(tpos * cf[d - HDh] + cp[d - HDh]);
            ten = cosf(100.f * cf[d - HDh] + cp[d - HDh]);
        }
        float w = W_ih[j * 248 + 200 + d];
        sp += w * tep;
        sn += w * ten;
    }
    g_biasP[j] = sp;
    g_biasN[j] = sn;
}

// ---------------- GRU update + l2n (block per node) ----------------
__global__ void gru_kernel(const float* __restrict__ b_hh) {
    int n = blockIdx.x, c = threadIdx.x;
    const float* bp = (g_deg[n] > 0) ? g_biasP : g_biasN;
    float v = 0.f;
    if (c < H) {
        float ir = g_gi[n * 600 + c]       + bp[c];
        float iz = g_gi[n * 600 + 200 + c] + bp[200 + c];
        float in_ = g_gi[n * 600 + 400 + c] + bp[400 + c];
        float hr = g_gh[n * 600 + c]       + b_hh[c];
        float hz = g_gh[n * 600 + 200 + c] + b_hh[200 + c];
        float hn = g_gh[n * 600 + 400 + c] + b_hh[400 + c];
        float rg = 1.f / (1.f + expf(-(ir + hr)));
        float zg = 1.f / (1.f + expf(-(iz + hz)));
        float ng = tanhf(in_ + rg * hn);
        v = (1.f - zg) * ng + zg * g_prev[n * H + c];
    }
    __shared__ float red[256];
    red[threadIdx.x] = v * v;
    __syncthreads();
    for (int off = 128; off; off >>= 1) {
        if (threadIdx.x < off) red[threadIdx.x] += red[threadIdx.x + off];
        __syncthreads();
    }
    float sc = 1.f / fmaxf(sqrtf(red[0]), 1e-12f);
    if (c < H) g_prev[n * H + c] = v * sc;
}

// ---------------- phase 2: history summaries ----------------
__global__ void tmp_kernel(const int* __restrict__ his_idx, const int* __restrict__ his_len) {
    int b = blockIdx.x, k = blockIdx.y, c = threadIdx.x;
    int ln = his_len[b * 3 + k];
    float s = 0.f;
    if (c < H) {
        for (int l = 0; l < ln; l++) {
            int idx = his_idx[(b * 3 + k) * 32 + l];
            s += g_prev[idx * H + c];
        }
    }
    float v = s / fmaxf((float)ln, 1.f);
    __shared__ float red[256];
    red[threadIdx.x] = (c < H) ? v * v : 0.f;
    __syncthreads();
    for (int off = 128; off; off >>= 1) {
        if (threadIdx.x < off) red[threadIdx.x] += red[threadIdx.x + off];
        __syncthreads();
    }
    float sc = 1.f / fmaxf(sqrtf(red[0]), 1e-12f);
    if (c < H) g_sbuf[k][b * H + c] = v * sc;
}

__global__ void cat_kernel(int k, float timk, const int* __restrict__ data,
                           const int* __restrict__ his_len,
                           const float* __restrict__ af, const float* __restrict__ ap,
                           const float* __restrict__ cf, const float* __restrict__ cp) {
    int b = blockIdx.x, c = threadIdx.x;
    int si = data[b * 4 + 0], ri = data[b * 4 + 1];
    if (c < H) {
        g_cat[b * 648 + c]       = g_prev[si * H + c];
        g_cat[b * 648 + 200 + c] = g_reln[ri * H + c];
        g_cat[b * 648 + 400 + c] = g_sbuf[k][b * H + c];
    }
    if (c < TD) {
        int ln = his_len[b * 3 + k];
        float t = (ln > 0) ? timk : 100.f;
        float v = (c < HDh) ? tanhf((t + 1.f) * af[c] + ap[c])
                            : cosf(t * cf[c - HDh] + cp[c - HDh]);
        g_cat[b * 648 + 600 + c] = v;
    }
}

__global__ void atts_kernel(int k, const float* __restrict__ Wc_w, const float* __restrict__ Wc_b) {
    int warp = (blockIdx.x * blockDim.x + threadIdx.x) >> 5;
    int lane = threadIdx.x & 31;
    if (warp >= NB) return;
    float s = 0.f;
    for (int c = lane; c < H; c += 32) s += g_abuf[warp * H + c] * Wc_w[c];
#pragma unroll
    for (int off = 16; off; off >>= 1) s += __shfl_xor_sync(0xffffffffu, s, off);
    if (lane == 0) g_atts[warp * 3 + k] = s + Wc_b[0];
}

__global__ void combine_kernel(const int* __restrict__ data) {
    int b = blockIdx.x, c = threadIdx.x;
    float a0 = g_atts[b * 3 + 0], a1 = g_atts[b * 3 + 1], a2 = g_atts[b * 3 + 2];
    float m = fmaxf(a0, fmaxf(a1, a2));
    float e0 = expf(a0 - m), e1 = expf(a1 - m), e2 = expf(a2 - m);
    float inv = 1.f / (e0 + e1 + e2);
    if (c < H) {
        int si = data[b * 4 + 0], ri = data[b * 4 + 1];
        float o2 = (e0 * g_sbuf[0][b * H + c] + e1 * g_sbuf[1][b * H + c] +
                    e2 * g_sbuf[2][b * H + c]) * inv;
        g_cat600[b * 600 + c]       = g_prev[si * H + c];
        g_cat600[b * 600 + 200 + c] = g_reln[ri * H + c];
        g_cat600[b * 600 + 400 + c] = o2;
    }
}

// ---------------- host orchestration ----------------
static inline dim3 gemm_grid(int N, int M) { return dim3((N + 63) / 64, (M + 127) / 128); }

extern "C" void kernel_launch(void* const* d_in, const int* in_sizes, int n_in,
                              void* d_out, int out_size) {
    (void)in_sizes; (void)n_in; (void)out_size;
    const int*   src    = (const int*)d_in[0];
    const int*   dst    = (const int*)d_in[1];
    const int*   etype  = (const int*)d_in[2];
    const int*   data   = (const int*)d_in[3];
    const int*   hisidx = (const int*)d_in[4];
    const int*   hislen = (const int*)d_in[5];
    const float* ent    = (const float*)d_in[6];
    const float* loopw  = (const float*)d_in[7];
    const float* rel    = (const float*)d_in[8];
    const float* absf   = (const float*)d_in[9];
    const float* absp   = (const float*)d_in[10];
    const float* cosfr  = (const float*)d_in[11];
    const float* cosph  = (const float*)d_in[12];
    const float* Wn     = (const float*)d_in[13];
    const float* Wsm    = (const float*)d_in[14];
    const float* W_ih   = (const float*)d_in[15];
    const float* W_hh   = (const float*)d_in[16];
    const float* b_ih   = (const float*)d_in[17];
    const float* b_hh   = (const float*)d_in[18];
    const float* Wb_w   = (const float*)d_in[19];
    const float* Wb_b   = (const float*)d_in[20];
    const float* Wc_w   = (const float*)d_in[21];
    const float* Wc_b   = (const float*)d_in[22];
    const float* Wd_w   = (const float*)d_in[23];
    const float* Wd_b   = (const float*)d_in[24];
    float* outp = (float*)d_out;

    float *prev, *hA, *hB, *pre, *gi, *gh, *reln, *cat, *cat600, *abuf, *qb;
    int* degp;
    void* p;
    cudaGetSymbolAddress(&p, g_prev);   prev   = (float*)p;
    cudaGetSymbolAddress(&p, g_hA);     hA     = (float*)p;
    cudaGetSymbolAddress(&p, g_hB);     hB     = (float*)p;
    cudaGetSymbolAddress(&p, g_pre);    pre    = (float*)p;
    cudaGetSymbolAddress(&p, g_gi);     gi     = (float*)p;
    cudaGetSymbolAddress(&p, g_gh);     gh     = (float*)p;
    cudaGetSymbolAddress(&p, g_reln);   reln   = (float*)p;
    cudaGetSymbolAddress(&p, g_cat);    cat    = (float*)p;
    cudaGetSymbolAddress(&p, g_cat600); cat600 = (float*)p;
    cudaGetSymbolAddress(&p, g_abuf);   abuf   = (float*)p;
    cudaGetSymbolAddress(&p, g_q);      qb     = (float*)p;
    cudaGetSymbolAddress(&p, g_deg);    degp   = (int*)p;

    const dim3 l2nBlk(32, 8);

    // rel_n = l2n(rel)
    l2n_kernel<<<(400 + 7) / 8, l2nBlk>>>(rel, reln, 400);
    // prev = l2n(ent @ loop_weight)
    sgemm_kernel<false, false, false, false><<<gemm_grid(H, NE), 256>>>(
        ent, H, loopw, H, nullptr, nullptr, nullptr, pre, H, NE, H, H);
    l2n_kernel<<<(NE + 7) / 8, l2nBlk>>>(pre, prev, NE);

    for (int i = 0; i < 3; i++) {
        cudaMemsetAsync(degp, 0, NE * sizeof(int), 0);
        count_kernel<<<(EE + 511) / 512, 512>>>(dst + i * EE);
        scan_kernel<<<1, 1024>>>();
        fill_kernel<<<(EE + 511) / 512, 512>>>(src + i * EE, dst + i * EE, etype + i * EE);
        gather1_kernel<<<NE, 256>>>();
        tebias_kernel<<<3, 256>>>(W_ih, b_ih, absf, absp, cosfr, cosph, (float)(2 - i));
        // layer 0: hB = relu(pre @ Wn[0] + hA @ Ws[0])
        gather2_kernel<<<NE, 256>>>(hA);
        sgemm_kernel<false, true, true, false><<<gemm_grid(H, NE), 256>>>(
            pre, H, Wn, H, hA, Wsm, nullptr, hB, H, NE, H, H);
        // layer 1: hA = relu(pre @ Wn[1] + hB @ Ws[1])
        gather2_kernel<<<NE, 256>>>(hB);
        sgemm_kernel<false, true, true, false><<<gemm_grid(H, NE), 256>>>(
            pre, H, Wn + H * H, H, hB, Wsm + H * H, nullptr, hA, H, NE, H, H);
        l2n_kernel<<<(NE + 7) / 8, l2nBlk>>>(hA, hA, NE);
        // GRU gates
        sgemm_kernel<true, false, false, false><<<gemm_grid(3 * H, NE), 256>>>(
            hA, H, W_ih, 248, nullptr, nullptr, nullptr, gi, 3 * H, NE, 3 * H, H);
        sgemm_kernel<true, false, false, false><<<gemm_grid(3 * H, NE), 256>>>(
            prev, H, W_hh, H, nullptr, nullptr, nullptr, gh, 3 * H, NE, 3 * H, H);
        gru_kernel<<<NE, 256>>>(b_hh);
    }

    // ---- phase 2: batch attention over histories ----
    tmp_kernel<<<dim3(NB, 3), 256>>>(hisidx, hislen);
    for (int k = 0; k < 3; k++) {
        cat_kernel<<<NB, 256>>>(k, (float)(2 - k), data, hislen, absf, absp, cosfr, cosph);
        sgemm_kernel<true, false, true, true><<<gemm_grid(H, NB), 256>>>(
            cat, 648, Wb_w, 648, nullptr, nullptr, Wb_b, abuf, H, NB, H, 648);
        atts_kernel<<<64, 256>>>(k, Wc_w, Wc_b);
    }
    combine_kernel<<<NB, 256>>>(data);
    sgemm_kernel<true, false, true, true><<<gemm_grid(H, NB), 256>>>(
        cat600, 600, Wd_w, 600, nullptr, nullptr, Wd_b, qb, H, NB, H, 600);
    // result = q @ out^T
    sgemm_kernel<true, false, false, false><<<gemm_grid(NE, NB), 256>>>(
        qb, H, prev, H, nullptr, nullptr, nullptr, outp, NE, NB, NE, H);
}

// round 7
// speedup vs baseline: 1.7538x; 1.1580x over previous
#include <cuda_runtime.h>
#include <math.h>
#include <stdint.h>

// ---------------- problem constants ----------------
constexpr int NE  = 20000;   // NUM_E
constexpr int H   = 200;
constexpr int EE  = 200000;  // E
constexpr int NB  = 512;     // BATCH
constexpr int TD  = 48;
constexpr int HDh = 24;      // TD/2

// ---------------- device scratch (no allocs allowed) ----------------
__device__ float g_prev[NE * H];
__device__ float g_hA[NE * H];
__device__ float g_hB[NE * H];
__device__ float g_pre[NE * H];
__device__ float g_relS[NE * H];
__device__ float g_gi[NE * 3 * H];
__device__ float g_gh[NE * 3 * H];
__device__ float g_reln[400 * H];
__device__ int   g_deg[NE];
__device__ int   g_rowptr[NE + 1];
__device__ int   g_cursor[NE];
__device__ int   g_esrc[EE];
__device__ int   g_erel[EE];
__device__ float g_biasP[3 * H];
__device__ float g_biasN[3 * H];
__device__ float g_sbuf[3][NB * H];
__device__ float g_cat[NB * 648];
__device__ float g_abuf[NB * H];
__device__ float g_atts[NB * 3];
__device__ float g_cat600[NB * 600];
__device__ float g_q[NB * H];

// ---------------- TF32 tensor-core GEMM ----------------
__device__ __forceinline__ uint32_t to_tf32(float x) {
    uint32_t r;
    asm("cvt.rna.tf32.f32 %0, %1;" : "=r"(r) : "f"(x));
    return r;
}

__device__ __forceinline__ void mma_tf32(float* d, const uint32_t* a, const uint32_t* b) {
    asm volatile(
        "mma.sync.aligned.m16n8k8.row.col.f32.tf32.tf32.f32 "
        "{%0,%1,%2,%3}, {%4,%5,%6,%7}, {%8,%9}, {%0,%1,%2,%3};"
        : "+f"(d[0]), "+f"(d[1]), "+f"(d[2]), "+f"(d[3])
        : "r"(a[0]), "r"(a[1]), "r"(a[2]), "r"(a[3]), "r"(b[0]), "r"(b[1]));
}

// C[M,N] = A[M,K] @ op(B) (+ A2 @ op(B2) if DUAL) (+ bias if BIAS), relu if RELU
// TRB: B stored [N, ldb], used transposed. Requirements: K%8==0; lda, ldb, N
// multiples of 4; ldc, N even.
template <bool TRB, bool DUAL, bool RELU, bool BIAS>
__global__ void __launch_bounds__(256, 2) sgemm_kernel(
    const float* __restrict__ A, int lda,
    const float* __restrict__ B, int ldb,
    const float* __restrict__ A2, const float* __restrict__ B2,
    const float* __restrict__ bias,
    float* __restrict__ C, int ldc, int M, int N, int K) {
    constexpr int BM = 128, BN = 64, BK = 8;
    __shared__ uint32_t As[2][BK][BM];   // [k][m], m XOR-swizzled by (k&3)*8
    __shared__ uint32_t Bs[2][BK][BN];   // [k][n], n XOR-swizzled by (k&3)*8
    const int bm = blockIdx.y * BM;
    const int bn = blockIdx.x * BN;
    const int t  = threadIdx.x;          // 256 threads
    const int lane = t & 31, warp = t >> 5;
    const int g = lane >> 2, tig = lane & 3;
    const int m0w = (warp & 3) * 32;     // warp M offset within tile
    const int n0w = (warp >> 2) * 32;    // warp N offset within tile

    // A staging: 128 rows x 8 k = 256 float4
    const int arow = t >> 1;
    const int akp  = (t & 1) * 4;
    // B staging (first 128 threads)
    const int bkk = t >> 4;          // non-TRB: k row (0..7)
    const int bnp = (t & 15) * 4;    // non-TRB: n group
    const int brow = t >> 1;         // TRB: n (0..63)
    const int bkp  = (t & 1) * 4;    // TRB: k part

    const int ksteps = K / BK;
    const int nsteps = (DUAL ? 2 : 1) * ksteps;

    float acc[2][4][4] = {};             // [mt][nt][frag]
    float4 aReg = make_float4(0.f, 0.f, 0.f, 0.f);
    float4 bReg = make_float4(0.f, 0.f, 0.f, 0.f);

    auto load_step = [&](int s) {
        int pass = DUAL ? (s >= ksteps ? 1 : 0) : 0;
        int k0 = (s - pass * ksteps) * BK;
        const float* Ap = pass ? A2 : A;
        const float* Bp = pass ? B2 : B;
        int gm = bm + arow;
        aReg = (gm < M) ? *(const float4*)(Ap + (size_t)gm * lda + k0 + akp)
                        : make_float4(0.f, 0.f, 0.f, 0.f);
        if (t < 128) {
            if (TRB) {
                int gn = bn + brow;
                bReg = (gn < N) ? *(const float4*)(Bp + (size_t)gn * ldb + k0 + bkp)
                                : make_float4(0.f, 0.f, 0.f, 0.f);
            } else {
                int gn = bn + bnp;
                bReg = (gn < N) ? *(const float4*)(Bp + (size_t)(k0 + bkk) * ldb + gn)
                                : make_float4(0.f, 0.f, 0.f, 0.f);
            }
        }
    };

    auto store_smem = [&](int buf) {
        float av[4] = {aReg.x, aReg.y, aReg.z, aReg.w};
#pragma unroll
        for (int j = 0; j < 4; j++) {
            int kk = akp + j;
            As[buf][kk][arow ^ ((kk & 3) * 8)] = to_tf32(av[j]);
        }
        if (t < 128) {
            float bv[4] = {bReg.x, bReg.y, bReg.z, bReg.w};
            if (TRB) {
#pragma unroll
                for (int j = 0; j < 4; j++) {
                    int kk = bkp + j;
                    Bs[buf][kk][brow ^ ((kk & 3) * 8)] = to_tf32(bv[j]);
                }
            } else {
#pragma unroll
                for (int j = 0; j < 4; j++) {
                    Bs[buf][bkk][(bnp + j) ^ ((bkk & 3) * 8)] = to_tf32(bv[j]);
                }
            }
        }
    };

    auto compute = [&](int buf) {
        uint32_t a[2][4];
#pragma unroll
        for (int mt = 0; mt < 2; mt++) {
            int mb = m0w + mt * 16 + g;
            a[mt][0] = As[buf][tig    ][(mb    ) ^ (tig * 8)];
            a[mt][1] = As[buf][tig    ][(mb + 8) ^ (tig * 8)];
            a[mt][2] = As[buf][tig + 4][(mb    ) ^ (tig * 8)];
            a[mt][3] = As[buf][tig + 4][(mb + 8) ^ (tig * 8)];
        }
        uint32_t b[4][2];
#pragma unroll
        for (int nt = 0; nt < 4; nt++) {
            int nb = n0w + nt * 8 + g;
            b[nt][0] = Bs[buf][tig    ][nb ^ (tig * 8)];
            b[nt][1] = Bs[buf][tig + 4][nb ^ (tig * 8)];
        }
#pragma unroll
        for (int mt = 0; mt < 2; mt++)
#pragma unroll
            for (int nt = 0; nt < 4; nt++)
                mma_tf32(acc[mt][nt], a[mt], b[nt]);
    };

    load_step(0);
    store_smem(0);
    __syncthreads();
    int buf = 0;
    for (int s = 1; s < nsteps; s++) {
        load_step(s);
        compute(buf);
        store_smem(buf ^ 1);
        __syncthreads();
        buf ^= 1;
    }
    compute(buf);

    // epilogue: c0,c1 at (g, 2*tig..2*tig+1), c2,c3 at (g+8, ...)
#pragma unroll
    for (int mt = 0; mt < 2; mt++) {
#pragma unroll
        for (int nt = 0; nt < 4; nt++) {
            int gm = bm + m0w + mt * 16 + g;
            int gn = bn + n0w + nt * 8 + 2 * tig;
            if (gn >= N) continue;
            float b0 = 0.f, b1 = 0.f;
            if (BIAS) { b0 = bias[gn]; b1 = bias[gn + 1]; }
            float v0 = acc[mt][nt][0] + b0, v1 = acc[mt][nt][1] + b1;
            float v2 = acc[mt][nt][2] + b0, v3 = acc[mt][nt][3] + b1;
            if (RELU) {
                v0 = fmaxf(v0, 0.f); v1 = fmaxf(v1, 0.f);
                v2 = fmaxf(v2, 0.f); v3 = fmaxf(v3, 0.f);
            }
            if (gm < M)     *(float2*)(C + (size_t)gm * ldc + gn)       = make_float2(v0, v1);
            if (gm + 8 < M) *(float2*)(C + (size_t)(gm + 8) * ldc + gn) = make_float2(v2, v3);
        }
    }
}

// ---------------- row L2 normalize (warp per row) ----------------
__global__ void l2n_kernel(const float* __restrict__ in, float* __restrict__ outp, int rows) {
    int r = blockIdx.x * blockDim.y + threadIdx.y;
    if (r >= rows) return;
    int lane = threadIdx.x;
    float s = 0.f;
    for (int c = lane; c < H; c += 32) { float v = in[r * H + c]; s += v * v; }
#pragma unroll
    for (int off = 16; off; off >>= 1) s += __shfl_xor_sync(0xffffffffu, s, off);
    float sc = 1.f / fmaxf(sqrtf(s), 1e-12f);
    for (int c = lane; c < H; c += 32) outp[r * H + c] = in[r * H + c] * sc;
}

// ---------------- CSR build ----------------
__global__ void count_kernel(const int* __restrict__ dsti) {
    int e = blockIdx.x * blockDim.x + threadIdx.x;
    if (e < EE) atomicAdd(&g_deg[dsti[e]], 1);
}

__global__ void scan_kernel() {
    __shared__ int s[1024];
    int t = threadIdx.x;
    int start = t * 20;
    int end = min(start + 20, NE);
    int local = 0;
    for (int i = start; i < end; i++) local += g_deg[i];
    s[t] = local;
    __syncthreads();
    for (int off = 1; off < 1024; off <<= 1) {
        int v = (t >= off) ? s[t - off] : 0;
        __syncthreads();
        s[t] += v;
        __syncthreads();
    }
    int run = s[t] - local;
    for (int i = start; i < end; i++) {
        g_rowptr[i] = run;
        g_cursor[i] = run;
        run += g_deg[i];
    }
    if (t == 1023) g_rowptr[NE] = run;
}

__global__ void fill_kernel(const int* __restrict__ srci, const int* __restrict__ dsti,
                            const int* __restrict__ eti) {
    int e = blockIdx.x * blockDim.x + threadIdx.x;
    if (e < EE) {
        int p = atomicAdd(&g_cursor[dsti[e]], 1);
        g_esrc[p] = srci[e];
        g_erel[p] = eti[e];
    }
}

// ---------------- aggregation passes (CSR gather, no float atomics) ----------------
__global__ void gather1_kernel() {
    int n = blockIdx.x, c = threadIdx.x;
    int b0 = g_rowptr[n], e0 = g_rowptr[n + 1];
    float s1 = 0.f, s2 = 0.f;
    if (c < H) {
        for (int i = b0; i < e0; i++) {
            s1 += g_prev[g_esrc[i] * H + c];
            s2 += g_reln[g_erel[i] * H + c];
        }
    }
    float inv = 1.f / fmaxf((float)(e0 - b0), 1.f);
    float v = s1 * inv;
    __shared__ float red[256];
    red[threadIdx.x] = (c < H) ? v * v : 0.f;
    __syncthreads();
    for (int off = 128; off; off >>= 1) {
        if (threadIdx.x < off) red[threadIdx.x] += red[threadIdx.x + off];
        __syncthreads();
    }
    float sc = 1.f / fmaxf(sqrtf(red[0]), 1e-12f);
    if (c < H) {
        g_hA[n * H + c] = v * sc;
        g_relS[n * H + c] = s2;
    }
}

__global__ void gather2_kernel(const float* __restrict__ hsrc) {
    int n = blockIdx.x, c = threadIdx.x;
    if (c >= H) return;
    int b0 = g_rowptr[n], e0 = g_rowptr[n + 1];
    float s = 0.f;
    for (int i = b0; i < e0; i++) s += hsrc[g_esrc[i] * H + c];
    float inv = 1.f / fmaxf((float)(e0 - b0), 1.f);
    g_pre[n * H + c] = (s + g_relS[n * H + c]) * inv;
}

// ---------------- time-encoding bias ----------------
__global__ void tebias_kernel(const float* __restrict__ W_ih, const float* __restrict__ b_ih,
                              const float* __restrict__ af, const float* __restrict__ ap,
                              const float* __restrict__ cf, const float* __restrict__ cp,
                              float tpos) {
    int j = blockIdx.x * blockDim.x + threadIdx.x;
    if (j >= 3 * H) return;
    float sp = b_ih[j], sn = b_ih[j];
    for (int d = 0; d < TD; d++) {
        float tep, ten;
        if (d < HDh) {
            tep = tanhf((tpos + 1.f) * af[d] + ap[d]);
            ten = tanhf(101.f * af[d] + ap[d]);
        } else {
            tep = cosf(tpos * cf[d - HDh] + cp[d - HDh]);
            ten = cosf(100.f * cf[d - HDh] + cp[d - HDh]);
        }
        float w = W_ih[j * 248 + 200 + d];
        sp += w * tep;
        sn += w * ten;
    }
    g_biasP[j] = sp;
    g_biasN[j] = sn;
}

// ---------------- GRU update + l2n (block per node) ----------------
__global__ void gru_kernel(const float* __restrict__ b_hh) {
    int n = blockIdx.x, c = threadIdx.x;
    const float* bp = (g_deg[n] > 0) ? g_biasP : g_biasN;
    float v = 0.f;
    if (c < H) {
        float ir = g_gi[n * 600 + c]       + bp[c];
        float iz = g_gi[n * 600 + 200 + c] + bp[200 + c];
        float in_ = g_gi[n * 600 + 400 + c] + bp[400 + c];
        float hr = g_gh[n * 600 + c]       + b_hh[c];
        float hz = g_gh[n * 600 + 200 + c] + b_hh[200 + c];
        float hn = g_gh[n * 600 + 400 + c] + b_hh[400 + c];
        float rg = 1.f / (1.f + expf(-(ir + hr)));
        float zg = 1.f / (1.f + expf(-(iz + hz)));
        float ng = tanhf(in_ + rg * hn);
        v = (1.f - zg) * ng + zg * g_prev[n * H + c];
    }
    __shared__ float red[256];
    red[threadIdx.x] = v * v;
    __syncthreads();
    for (int off = 128; off; off >>= 1) {
        if (threadIdx.x < off) red[threadIdx.x] += red[threadIdx.x + off];
        __syncthreads();
    }
    float sc = 1.f / fmaxf(sqrtf(red[0]), 1e-12f);
    if (c < H) g_prev[n * H + c] = v * sc;
}

// ---------------- phase 2: history summaries ----------------
__global__ void tmp_kernel(const int* __restrict__ his_idx, const int* __restrict__ his_len) {
    int b = blockIdx.x, k = blockIdx.y, c = threadIdx.x;
    int ln = his_len[b * 3 + k];
    float s = 0.f;
    if (c < H) {
        for (int l = 0; l < ln; l++) {
            int idx = his_idx[(b * 3 + k) * 32 + l];
            s += g_prev[idx * H + c];
        }
    }
    float v = s / fmaxf((float)ln, 1.f);
    __shared__ float red[256];
    red[threadIdx.x] = (c < H) ? v * v : 0.f;
    __syncthreads();
    for (int off = 128; off; off >>= 1) {
        if (threadIdx.x < off) red[threadIdx.x] += red[threadIdx.x + off];
        __syncthreads();
    }
    float sc = 1.f / fmaxf(sqrtf(red[0]), 1e-12f);
    if (c < H) g_sbuf[k][b * H + c] = v * sc;
}

__global__ void cat_kernel(int k, float timk, const int* __restrict__ data,
                           const int* __restrict__ his_len,
                           const float* __restrict__ af, const float* __restrict__ ap,
                           const float* __restrict__ cf, const float* __restrict__ cp) {
    int b = blockIdx.x, c = threadIdx.x;
    int si = data[b * 4 + 0], ri = data[b * 4 + 1];
    if (c < H) {
        g_cat[b * 648 + c]       = g_prev[si * H + c];
        g_cat[b * 648 + 200 + c] = g_reln[ri * H + c];
        g_cat[b * 648 + 400 + c] = g_sbuf[k][b * H + c];
    }
    if (c < TD) {
        int ln = his_len[b * 3 + k];
        float t = (ln > 0) ? timk : 100.f;
        float v = (c < HDh) ? tanhf((t + 1.f) * af[c] + ap[c])
                            : cosf(t * cf[c - HDh] + cp[c - HDh]);
        g_cat[b * 648 + 600 + c] = v;
    }
}

__global__ void atts_kernel(int k, const float* __restrict__ Wc_w, const float* __restrict__ Wc_b) {
    int warp = (blockIdx.x * blockDim.x + threadIdx.x) >> 5;
    int lane = threadIdx.x & 31;
    if (warp >= NB) return;
    float s = 0.f;
    for (int c = lane; c < H; c += 32) s += g_abuf[warp * H + c] * Wc_w[c];
#pragma unroll
    for (int off = 16; off; off >>= 1) s += __shfl_xor_sync(0xffffffffu, s, off);
    if (lane == 0) g_atts[warp * 3 + k] = s + Wc_b[0];
}

__global__ void combine_kernel(const int* __restrict__ data) {
    int b = blockIdx.x, c = threadIdx.x;
    float a0 = g_atts[b * 3 + 0], a1 = g_atts[b * 3 + 1], a2 = g_atts[b * 3 + 2];
    float m = fmaxf(a0, fmaxf(a1, a2));
    float e0 = expf(a0 - m), e1 = expf(a1 - m), e2 = expf(a2 - m);
    float inv = 1.f / (e0 + e1 + e2);
    if (c < H) {
        int si = data[b * 4 + 0], ri = data[b * 4 + 1];
        float o2 = (e0 * g_sbuf[0][b * H + c] + e1 * g_sbuf[1][b * H + c] +
                    e2 * g_sbuf[2][b * H + c]) * inv;
        g_cat600[b * 600 + c]       = g_prev[si * H + c];
        g_cat600[b * 600 + 200 + c] = g_reln[ri * H + c];
        g_cat600[b * 600 + 400 + c] = o2;
    }
}

// ---------------- host orchestration ----------------
static inline dim3 gemm_grid(int N, int M) { return dim3((N + 63) / 64, (M + 127) / 128); }

extern "C" void kernel_launch(void* const* d_in, const int* in_sizes, int n_in,
                              void* d_out, int out_size) {
    (void)in_sizes; (void)n_in; (void)out_size;
    const int*   src    = (const int*)d_in[0];
    const int*   dst    = (const int*)d_in[1];
    const int*   etype  = (const int*)d_in[2];
    const int*   data   = (const int*)d_in[3];
    const int*   hisidx = (const int*)d_in[4];
    const int*   hislen = (const int*)d_in[5];
    const float* ent    = (const float*)d_in[6];
    const float* loopw  = (const float*)d_in[7];
    const float* rel    = (const float*)d_in[8];
    const float* absf   = (const float*)d_in[9];
    const float* absp   = (const float*)d_in[10];
    const float* cosfr  = (const float*)d_in[11];
    const float* cosph  = (const float*)d_in[12];
    const float* Wn     = (const float*)d_in[13];
    const float* Wsm    = (const float*)d_in[14];
    const float* W_ih   = (const float*)d_in[15];
    const float* W_hh   = (const float*)d_in[16];
    const float* b_ih   = (const float*)d_in[17];
    const float* b_hh   = (const float*)d_in[18];
    const float* Wb_w   = (const float*)d_in[19];
    const float* Wb_b   = (const float*)d_in[20];
    const float* Wc_w   = (const float*)d_in[21];
    const float* Wc_b   = (const float*)d_in[22];
    const float* Wd_w   = (const float*)d_in[23];
    const float* Wd_b   = (const float*)d_in[24];
    float* outp = (float*)d_out;

    float *prev, *hA, *hB, *pre, *gi, *gh, *reln, *cat, *cat600, *abuf, *qb;
    int* degp;
    void* p;
    cudaGetSymbolAddress(&p, g_prev);   prev   = (float*)p;
    cudaGetSymbolAddress(&p, g_hA);     hA     = (float*)p;
    cudaGetSymbolAddress(&p, g_hB);     hB     = (float*)p;
    cudaGetSymbolAddress(&p, g_pre);    pre    = (float*)p;
    cudaGetSymbolAddress(&p, g_gi);     gi     = (float*)p;
    cudaGetSymbolAddress(&p, g_gh);     gh     = (float*)p;
    cudaGetSymbolAddress(&p, g_reln);   reln   = (float*)p;
    cudaGetSymbolAddress(&p, g_cat);    cat    = (float*)p;
    cudaGetSymbolAddress(&p, g_cat600); cat600 = (float*)p;
    cudaGetSymbolAddress(&p, g_abuf);   abuf   = (float*)p;
    cudaGetSymbolAddress(&p, g_q);      qb     = (float*)p;
    cudaGetSymbolAddress(&p, g_deg);    degp   = (int*)p;

    const dim3 l2nBlk(32, 8);

    // rel_n = l2n(rel)
    l2n_kernel<<<(400 + 7) / 8, l2nBlk>>>(rel, reln, 400);
    // prev = l2n(ent @ loop_weight)
    sgemm_kernel<false, false, false, false><<<gemm_grid(H, NE), 256>>>(
        ent, H, loopw, H, nullptr, nullptr, nullptr, pre, H, NE, H, H);
    l2n_kernel<<<(NE + 7) / 8, l2nBlk>>>(pre, prev, NE);

    for (int i = 0; i < 3; i++) {
        cudaMemsetAsync(degp, 0, NE * sizeof(int), 0);
        count_kernel<<<(EE + 511) / 512, 512>>>(dst + i * EE);
        scan_kernel<<<1, 1024>>>();
        fill_kernel<<<(EE + 511) / 512, 512>>>(src + i * EE, dst + i * EE, etype + i * EE);
        gather1_kernel<<<NE, 256>>>();
        tebias_kernel<<<3, 256>>>(W_ih, b_ih, absf, absp, cosfr, cosph, (float)(2 - i));
        // layer 0: hB = relu(pre @ Wn[0] + hA @ Ws[0])
        gather2_kernel<<<NE, 256>>>(hA);
        sgemm_kernel<false, true, true, false><<<gemm_grid(H, NE), 256>>>(
            pre, H, Wn, H, hA, Wsm, nullptr, hB, H, NE, H, H);
        // layer 1: hA = relu(pre @ Wn[1] + hB @ Ws[1])
        gather2_kernel<<<NE, 256>>>(hB);
        sgemm_kernel<false, true, true, false><<<gemm_grid(H, NE), 256>>>(
            pre, H, Wn + H * H, H, hB, Wsm + H * H, nullptr, hA, H, NE, H, H);
        l2n_kernel<<<(NE + 7) / 8, l2nBlk>>>(hA, hA, NE);
        // GRU gates
        sgemm_kernel<true, false, false, false><<<gemm_grid(3 * H, NE), 256>>>(
            hA, H, W_ih, 248, nullptr, nullptr, nullptr, gi, 3 * H, NE, 3 * H, H);
        sgemm_kernel<true, false, false, false><<<gemm_grid(3 * H, NE), 256>>>(
            prev, H, W_hh, H, nullptr, nullptr, nullptr, gh, 3 * H, NE, 3 * H, H);
        gru_kernel<<<NE, 256>>>(b_hh);
    }

    // ---- phase 2: batch attention over histories ----
    tmp_kernel<<<dim3(NB, 3), 256>>>(hisidx, hislen);
    for (int k = 0; k < 3; k++) {
        cat_kernel<<<NB, 256>>>(k, (float)(2 - k), data, hislen, absf, absp, cosfr, cosph);
        sgemm_kernel<true, false, true, true><<<gemm_grid(H, NB), 256>>>(
            cat, 648, Wb_w, 648, nullptr, nullptr, Wb_b, abuf, H, NB, H, 648);
        atts_kernel<<<64, 256>>>(k, Wc_w, Wc_b);
    }
    combine_kernel<<<NB, 256>>>(data);
    sgemm_kernel<true, false, true, true><<<gemm_grid(H, NB), 256>>>(
        cat600, 600, Wd_w, 600, nullptr, nullptr, Wd_b, qb, H, NB, H, 600);
    // result = q @ out^T
    sgemm_kernel<true, false, false, false><<<gemm_grid(NE, NB), 256>>>(
        qb, H, prev, H, nullptr, nullptr, nullptr, outp, NE, NB, NE, H);
}

// round 10
// speedup vs baseline: 1.9795x; 1.1287x over previous
#include <cuda_runtime.h>
#include <math.h>
#include <stdint.h>

// ---------------- problem constants ----------------
constexpr int NE  = 20000;   // NUM_E
constexpr int H   = 200;
constexpr int EE  = 200000;  // E
constexpr int NB  = 512;     // BATCH
constexpr int TD  = 48;
constexpr int HDh = 24;      // TD/2

// ---------------- device scratch (no allocs allowed) ----------------
__device__ float g_prev[NE * H];
__device__ float g_hA[NE * H];
__device__ float g_hB[NE * H];
__device__ float g_pre[NE * H];
__device__ float g_relS[NE * H];
__device__ float g_gi[NE * 3 * H];
__device__ float g_gh[NE * 3 * H];
__device__ float g_reln[400 * H];
__device__ int   g_deg[NE];
__device__ int   g_rowptr[NE + 1];
__device__ int   g_cursor[NE];
__device__ int   g_esrc[EE];
__device__ int   g_erel[EE];
__device__ float g_biasP[3 * H];
__device__ float g_biasN[3 * H];
__device__ float g_sbuf[3][NB * H];
__device__ float g_cat[NB * 648];
__device__ float g_abuf[NB * H];
__device__ float g_atts[NB * 3];
__device__ float g_cat600[NB * 600];
__device__ float g_q[NB * H];

__device__ __forceinline__ float4 f4add(float4 a, float4 b) {
    return make_float4(a.x + b.x, a.y + b.y, a.z + b.z, a.w + b.w);
}
__device__ __forceinline__ float4 f4scale(float4 a, float s) {
    return make_float4(a.x * s, a.y * s, a.z * s, a.w * s);
}

// ---------------- TF32 tensor-core GEMM ----------------
__device__ __forceinline__ uint32_t to_tf32(float x) {
    uint32_t r;
    asm("cvt.rna.tf32.f32 %0, %1;" : "=r"(r) : "f"(x));
    return r;
}

__device__ __forceinline__ void mma_tf32(float* d, const uint32_t* a, const uint32_t* b) {
    asm volatile(
        "mma.sync.aligned.m16n8k8.row.col.f32.tf32.tf32.f32 "
        "{%0,%1,%2,%3}, {%4,%5,%6,%7}, {%8,%9}, {%0,%1,%2,%3};"
        : "+f"(d[0]), "+f"(d[1]), "+f"(d[2]), "+f"(d[3])
        : "r"(a[0]), "r"(a[1]), "r"(a[2]), "r"(a[3]), "r"(b[0]), "r"(b[1]));
}

// C[M,N] = A[M,K] @ op(B) (+ A2 @ op(B2) if DUAL) (+ bias if BIAS), relu if RELU
template <bool TRB, bool DUAL, bool RELU, bool BIAS>
__global__ void __launch_bounds__(256, 2) sgemm_kernel(
    const float* __restrict__ A, int lda,
    const float* __restrict__ B, int ldb,
    const float* __restrict__ A2, const float* __restrict__ B2,
    const float* __restrict__ bias,
    float* __restrict__ C, int ldc, int M, int N, int K) {
    constexpr int BM = 128, BN = 64, BK = 8;
    __shared__ uint32_t As[2][BK][BM];
    __shared__ uint32_t Bs[2][BK][BN];
    const int bm = blockIdx.y * BM;
    const int bn = blockIdx.x * BN;
    const int t  = threadIdx.x;
    const int lane = t & 31, warp = t >> 5;
    const int g = lane >> 2, tig = lane & 3;
    const int m0w = (warp & 3) * 32;
    const int n0w = (warp >> 2) * 32;

    const int arow = t >> 1;
    const int akp  = (t & 1) * 4;
    const int bkk = t >> 4;
    const int bnp = (t & 15) * 4;
    const int brow = t >> 1;
    const int bkp  = (t & 1) * 4;

    const int ksteps = K / BK;
    const int nsteps = (DUAL ? 2 : 1) * ksteps;

    float acc[2][4][4] = {};
    float4 aReg = make_float4(0.f, 0.f, 0.f, 0.f);
    float4 bReg = make_float4(0.f, 0.f, 0.f, 0.f);

    auto load_step = [&](int s) {
        int pass = DUAL ? (s >= ksteps ? 1 : 0) : 0;
        int k0 = (s - pass * ksteps) * BK;
        const float* Ap = pass ? A2 : A;
        const float* Bp = pass ? B2 : B;
        int gm = bm + arow;
        aReg = (gm < M) ? *(const float4*)(Ap + (size_t)gm * lda + k0 + akp)
                        : make_float4(0.f, 0.f, 0.f, 0.f);
        if (t < 128) {
            if (TRB) {
                int gn = bn + brow;
                bReg = (gn < N) ? *(const float4*)(Bp + (size_t)gn * ldb + k0 + bkp)
                                : make_float4(0.f, 0.f, 0.f, 0.f);
            } else {
                int gn = bn + bnp;
                bReg = (gn < N) ? *(const float4*)(Bp + (size_t)(k0 + bkk) * ldb + gn)
                                : make_float4(0.f, 0.f, 0.f, 0.f);
            }
        }
    };

    auto store_smem = [&](int buf) {
        float av[4] = {aReg.x, aReg.y, aReg.z, aReg.w};
#pragma unroll
        for (int j = 0; j < 4; j++) {
            int kk = akp + j;
            As[buf][kk][arow ^ ((kk & 3) * 8)] = to_tf32(av[j]);
        }
        if (t < 128) {
            float bv[4] = {bReg.x, bReg.y, bReg.z, bReg.w};
            if (TRB) {
#pragma unroll
                for (int j = 0; j < 4; j++) {
                    int kk = bkp + j;
                    Bs[buf][kk][brow ^ ((kk & 3) * 8)] = to_tf32(bv[j]);
                }
            } else {
#pragma unroll
                for (int j = 0; j < 4; j++) {
                    Bs[buf][bkk][(bnp + j) ^ ((bkk & 3) * 8)] = to_tf32(bv[j]);
                }
            }
        }
    };

    auto compute = [&](int buf) {
        uint32_t a[2][4];
#pragma unroll
        for (int mt = 0; mt < 2; mt++) {
            int mb = m0w + mt * 16 + g;
            a[mt][0] = As[buf][tig    ][(mb    ) ^ (tig * 8)];
            a[mt][1] = As[buf][tig    ][(mb + 8) ^ (tig * 8)];
            a[mt][2] = As[buf][tig + 4][(mb    ) ^ (tig * 8)];
            a[mt][3] = As[buf][tig + 4][(mb + 8) ^ (tig * 8)];
        }
        uint32_t b[4][2];
#pragma unroll
        for (int nt = 0; nt < 4; nt++) {
            int nb = n0w + nt * 8 + g;
            b[nt][0] = Bs[buf][tig    ][nb ^ (tig * 8)];
            b[nt][1] = Bs[buf][tig + 4][nb ^ (tig * 8)];
        }
#pragma unroll
        for (int mt = 0; mt < 2; mt++)
#pragma unroll
            for (int nt = 0; nt < 4; nt++)
                mma_tf32(acc[mt][nt], a[mt], b[nt]);
    };

    load_step(0);
    store_smem(0);
    __syncthreads();
    int buf = 0;
    for (int s = 1; s < nsteps; s++) {
        load_step(s);
        compute(buf);
        store_smem(buf ^ 1);
        __syncthreads();
        buf ^= 1;
    }
    compute(buf);

#pragma unroll
    for (int mt = 0; mt < 2; mt++) {
#pragma unroll
        for (int nt = 0; nt < 4; nt++) {
            int gm = bm + m0w + mt * 16 + g;
            int gn = bn + n0w + nt * 8 + 2 * tig;
            if (gn >= N) continue;
            float b0 = 0.f, b1 = 0.f;
            if (BIAS) { b0 = bias[gn]; b1 = bias[gn + 1]; }
            float v0 = acc[mt][nt][0] + b0, v1 = acc[mt][nt][1] + b1;
            float v2 = acc[mt][nt][2] + b0, v3 = acc[mt][nt][3] + b1;
            if (RELU) {
                v0 = fmaxf(v0, 0.f); v1 = fmaxf(v1, 0.f);
                v2 = fmaxf(v2, 0.f); v3 = fmaxf(v3, 0.f);
            }
            if (gm < M)     *(float2*)(C + (size_t)gm * ldc + gn)       = make_float2(v0, v1);
            if (gm + 8 < M) *(float2*)(C + (size_t)(gm + 8) * ldc + gn) = make_float2(v2, v3);
        }
    }
}

// ---------------- row L2 normalize (warp per row) ----------------
__global__ void l2n_kernel(const float* __restrict__ in, float* __restrict__ outp, int rows) {
    int r = blockIdx.x * blockDim.y + threadIdx.y;
    if (r >= rows) return;
    int lane = threadIdx.x;
    float s = 0.f;
    for (int c = lane; c < H; c += 32) { float v = in[r * H + c]; s += v * v; }
#pragma unroll
    for (int off = 16; off; off >>= 1) s += __shfl_xor_sync(0xffffffffu, s, off);
    float sc = 1.f / fmaxf(sqrtf(s), 1e-12f);
    for (int c = lane; c < H; c += 32) outp[r * H + c] = in[r * H + c] * sc;
}

// ---------------- CSR build ----------------
__global__ void count_kernel(const int* __restrict__ dsti) {
    int e = blockIdx.x * blockDim.x + threadIdx.x;
    if (e < EE) atomicAdd(&g_deg[dsti[e]], 1);
}

__global__ void scan_kernel() {
    __shared__ int s[1024];
    int t = threadIdx.x;
    int start = t * 20;
    int end = min(start + 20, NE);
    int local = 0;
    for (int i = start; i < end; i++) local += g_deg[i];
    s[t] = local;
    __syncthreads();
    for (int off = 1; off < 1024; off <<= 1) {
        int v = (t >= off) ? s[t - off] : 0;
        __syncthreads();
        s[t] += v;
        __syncthreads();
    }
    int run = s[t] - local;
    for (int i = start; i < end; i++) {
        g_rowptr[i] = run;
        g_cursor[i] = run;
        run += g_deg[i];
    }
    if (t == 1023) g_rowptr[NE] = run;
}

__global__ void fill_kernel(const int* __restrict__ srci, const int* __restrict__ dsti,
                            const int* __restrict__ eti) {
    int e = blockIdx.x * blockDim.x + threadIdx.x;
    if (e < EE) {
        int p = atomicAdd(&g_cursor[dsti[e]], 1);
        g_esrc[p] = srci[e];
        g_erel[p] = eti[e];
    }
}

// ---------------- vectorized CSR gathers ----------------
// block = 64 threads per node; threads 0..49 own one float4 column slice.
__global__ void __launch_bounds__(64) gather1_kernel() {
    int n = blockIdx.x;
    int t = threadIdx.x;
    int b0 = g_rowptr[n], e0 = g_rowptr[n + 1];
    int c = t * 4;
    float4 s1 = make_float4(0.f, 0.f, 0.f, 0.f);
    float4 s2 = make_float4(0.f, 0.f, 0.f, 0.f);
    if (t < 50) {
        int i = b0;
        for (; i + 4 <= e0; i += 4) {
            int a0 = g_esrc[i], a1 = g_esrc[i + 1], a2 = g_esrc[i + 2], a3 = g_esrc[i + 3];
            int r0 = g_erel[i], r1 = g_erel[i + 1], r2 = g_erel[i + 2], r3 = g_erel[i + 3];
            float4 v0 = *(const float4*)(g_prev + a0 * H + c);
            float4 v1 = *(const float4*)(g_prev + a1 * H + c);
            float4 v2 = *(const float4*)(g_prev + a2 * H + c);
            float4 v3 = *(const float4*)(g_prev + a3 * H + c);
            float4 w0 = *(const float4*)(g_reln + r0 * H + c);
            float4 w1 = *(const float4*)(g_reln + r1 * H + c);
            float4 w2 = *(const float4*)(g_reln + r2 * H + c);
            float4 w3 = *(const float4*)(g_reln + r3 * H + c);
            s1 = f4add(f4add(f4add(f4add(s1, v0), v1), v2), v3);
            s2 = f4add(f4add(f4add(f4add(s2, w0), w1), w2), w3);
        }
        for (; i < e0; i++) {
            s1 = f4add(s1, *(const float4*)(g_prev + g_esrc[i] * H + c));
            s2 = f4add(s2, *(const float4*)(g_reln + g_erel[i] * H + c));
        }
    }
    float inv = 1.f / fmaxf((float)(e0 - b0), 1.f);
    float4 v = f4scale(s1, inv);
    float ss = v.x * v.x + v.y * v.y + v.z * v.z + v.w * v.w;
#pragma unroll
    for (int off = 16; off; off >>= 1) ss += __shfl_xor_sync(0xffffffffu, ss, off);
    __shared__ float red[2];
    if ((t & 31) == 0) red[t >> 5] = ss;
    __syncthreads();
    float sc = 1.f / fmaxf(sqrtf(red[0] + red[1]), 1e-12f);
    if (t < 50) {
        *(float4*)(g_hA + n * H + c) = f4scale(v, sc);
        *(float4*)(g_relS + n * H + c) = s2;
    }
}

__global__ void __launch_bounds__(64) gather2_kernel(const float* __restrict__ hsrc) {
    int n = blockIdx.x;
    int t = threadIdx.x;
    if (t >= 50) return;
    int c = t * 4;
    int b0 = g_rowptr[n], e0 = g_rowptr[n + 1];
    float4 s = make_float4(0.f, 0.f, 0.f, 0.f);
    int i = b0;
    for (; i + 4 <= e0; i += 4) {
        int a0 = g_esrc[i], a1 = g_esrc[i + 1], a2 = g_esrc[i + 2], a3 = g_esrc[i + 3];
        float4 v0 = *(const float4*)(hsrc + a0 * H + c);
        float4 v1 = *(const float4*)(hsrc + a1 * H + c);
        float4 v2 = *(const float4*)(hsrc + a2 * H + c);
        float4 v3 = *(const float4*)(hsrc + a3 * H + c);
        s = f4add(f4add(f4add(f4add(s, v0), v1), v2), v3);
    }
    for (; i < e0; i++) s = f4add(s, *(const float4*)(hsrc + g_esrc[i] * H + c));
    float inv = 1.f / fmaxf((float)(e0 - b0), 1.f);
    float4 r = *(const float4*)(g_relS + n * H + c);
    *(float4*)(g_pre + n * H + c) = f4scale(f4add(s, r), inv);
}

// ---------------- time-encoding bias ----------------
__global__ void tebias_kernel(const float* __restrict__ W_ih, const float* __restrict__ b_ih,
                              const float* __restrict__ af, const float* __restrict__ ap,
                              const float* __restrict__ cf, const float* __restrict__ cp,
                              float tpos) {
    int j = blockIdx.x * blockDim.x + threadIdx.x;
    if (j >= 3 * H) return;
    float sp = b_ih[j], sn = b_ih[j];
    for (int d = 0; d < TD; d++) {
        float tep, ten;
        if (d < HDh) {
            tep = tanhf((tpos + 1.f) * af[d] + ap[d]);
            ten = tanhf(101.f * af[d] + ap[d]);
        } else {
            tep = cosf(tpos * cf[d - HDh] + cp[d - HDh]);
            ten = cosf(100.f * cf[d - HDh] + cp[d - HDh]);
        }
        float w = W_ih[j * 248 + 200 + d];
        sp += w * tep;
        sn += w * ten;
    }
    g_biasP[j] = sp;
    g_biasN[j] = sn;
}

// ---------------- GRU update + l2n (vectorized, 64 threads/node) ----------------
__global__ void __launch_bounds__(64) gru_kernel(const float* __restrict__ b_hh) {
    int n = blockIdx.x;
    int t = threadIdx.x;
    int c = t * 4;
    const float* bp = (g_deg[n] > 0) ? g_biasP : g_biasN;
    float4 v = make_float4(0.f, 0.f, 0.f, 0.f);
    if (t < 50) {
        float4 ir = *(const float4*)(g_gi + n * 600 + c);
        float4 iz = *(const float4*)(g_gi + n * 600 + 200 + c);
        float4 in_ = *(const float4*)(g_gi + n * 600 + 400 + c);
        float4 hr = *(const float4*)(g_gh + n * 600 + c);
        float4 hz = *(const float4*)(g_gh + n * 600 + 200 + c);
        float4 hn = *(const float4*)(g_gh + n * 600 + 400 + c);
        float4 pv = *(const float4*)(g_prev + n * H + c);
        float4 bp0 = *(const float4*)(bp + c);
        float4 bp1 = *(const float4*)(bp + 200 + c);
        float4 bp2 = *(const float4*)(bp + 400 + c);
        float4 bh0 = *(const float4*)(b_hh + c);
        float4 bh1 = *(const float4*)(b_hh + 200 + c);
        float4 bh2 = *(const float4*)(b_hh + 400 + c);
        float* vv = (float*)&v;
        const float *irp = (const float*)&ir, *izp = (const float*)&iz, *inp = (const float*)&in_;
        const float *hrp = (const float*)&hr, *hzp = (const float*)&hz, *hnp = (const float*)&hn;
        const float *pvp = (const float*)&pv;
        const float *b0p = (const float*)&bp0, *b1p = (const float*)&bp1, *b2p = (const float*)&bp2;
        const float *c0p = (const float*)&bh0, *c1p = (const float*)&bh1, *c2p = (const float*)&bh2;
#pragma unroll
        for (int j = 0; j < 4; j++) {
            float rsum = irp[j] + b0p[j] + hrp[j] + c0p[j];
            float zsum = izp[j] + b1p[j] + hzp[j] + c1p[j];
            float hnv  = hnp[j] + c2p[j];
            float rg = 1.f / (1.f + expf(-rsum));
            float zg = 1.f / (1.f + expf(-zsum));
            float ng = tanhf(inp[j] + b2p[j] + rg * hnv);
            vv[j] = (1.f - zg) * ng + zg * pvp[j];
        }
    }
    float ss = v.x * v.x + v.y * v.y + v.z * v.z + v.w * v.w;
#pragma unroll
    for (int off = 16; off; off >>= 1) ss += __shfl_xor_sync(0xffffffffu, ss, off);
    __shared__ float red[2];
    if ((t & 31) == 0) red[t >> 5] = ss;
    __syncthreads();
    float sc = 1.f / fmaxf(sqrtf(red[0] + red[1]), 1e-12f);
    if (t < 50) *(float4*)(g_prev + n * H + c) = f4scale(v, sc);
}

// ---------------- phase 2: history summaries (vectorized) ----------------
__global__ void __launch_bounds__(64) tmp_kernel(const int* __restrict__ his_idx,
                                                 const int* __restrict__ his_len) {
    int b = blockIdx.x, k = blockIdx.y;
    int t = threadIdx.x;
    int c = t * 4;
    int ln = his_len[b * 3 + k];
    const int* idxp = his_idx + (b * 3 + k) * 32;
    float4 s = make_float4(0.f, 0.f, 0.f, 0.f);
    if (t < 50) {
        int l = 0;
        for (; l + 4 <= ln; l += 4) {
            int a0 = idxp[l], a1 = idxp[l + 1], a2 = idxp[l + 2], a3 = idxp[l + 3];
            float4 v0 = *(const float4*)(g_prev + a0 * H + c);
            float4 v1 = *(const float4*)(g_prev + a1 * H + c);
            float4 v2 = *(const float4*)(g_prev + a2 * H + c);
            float4 v3 = *(const float4*)(g_prev + a3 * H + c);
            s = f4add(f4add(f4add(f4add(s, v0), v1), v2), v3);
        }
        for (; l < ln; l++) s = f4add(s, *(const float4*)(g_prev + idxp[l] * H + c));
    }
    float4 v = f4scale(s, 1.f / fmaxf((float)ln, 1.f));
    float ss = v.x * v.x + v.y * v.y + v.z * v.z + v.w * v.w;
#pragma unroll
    for (int off = 16; off; off >>= 1) ss += __shfl_xor_sync(0xffffffffu, ss, off);
    __shared__ float red[2];
    if ((t & 31) == 0) red[t >> 5] = ss;
    __syncthreads();
    float sc = 1.f / fmaxf(sqrtf(red[0] + red[1]), 1e-12f);
    if (t < 50) *(float4*)(&g_sbuf[k][b * H + c]) = f4scale(v, sc);
}

__global__ void cat_kernel(int k, float timk, const int* __restrict__ data,
                           const int* __restrict__ his_len,
                           const float* __restrict__ af, const float* __restrict__ ap,
                           const float* __restrict__ cf, const float* __restrict__ cp) {
    int b = blockIdx.x, c = threadIdx.x;
    int si = data[b * 4 + 0], ri = data[b * 4 + 1];
    if (c < H) {
        g_cat[b * 648 + c]       = g_prev[si * H + c];
        g_cat[b * 648 + 200 + c] = g_reln[ri * H + c];
        g_cat[b * 648 + 400 + c] = g_sbuf[k][b * H + c];
    }
    if (c < TD) {
        int ln = his_len[b * 3 + k];
        float t = (ln > 0) ? timk : 100.f;
        float v = (c < HDh) ? tanhf((t + 1.f) * af[c] + ap[c])
                            : cosf(t * cf[c - HDh] + cp[c - HDh]);
        g_cat[b * 648 + 600 + c] = v;
    }
}

__global__ void atts_kernel(int k, const float* __restrict__ Wc_w, const float* __restrict__ Wc_b) {
    int warp = (blockIdx.x * blockDim.x + threadIdx.x) >> 5;
    int lane = threadIdx.x & 31;
    if (warp >= NB) return;
    float s = 0.f;
    for (int c = lane; c < H; c += 32) s += g_abuf[warp * H + c] * Wc_w[c];
#pragma unroll
    for (int off = 16; off; off >>= 1) s += __shfl_xor_sync(0xffffffffu, s, off);
    if (lane == 0) g_atts[warp * 3 + k] = s + Wc_b[0];
}

__global__ void combine_kernel(const int* __restrict__ data) {
    int b = blockIdx.x, c = threadIdx.x;
    float a0 = g_atts[b * 3 + 0], a1 = g_atts[b * 3 + 1], a2 = g_atts[b * 3 + 2];
    float m = fmaxf(a0, fmaxf(a1, a2));
    float e0 = expf(a0 - m), e1 = expf(a1 - m), e2 = expf(a2 - m);
    float inv = 1.f / (e0 + e1 + e2);
    if (c < H) {
        int si = data[b * 4 + 0], ri = data[b * 4 + 1];
        float o2 = (e0 * g_sbuf[0][b * H + c] + e1 * g_sbuf[1][b * H + c] +
                    e2 * g_sbuf[2][b * H + c]) * inv;
        g_cat600[b * 600 + c]       = g_prev[si * H + c];
        g_cat600[b * 600 + 200 + c] = g_reln[ri * H + c];
        g_cat600[b * 600 + 400 + c] = o2;
    }
}

// ---------------- host orchestration ----------------
static inline dim3 gemm_grid(int N, int M) { return dim3((N + 63) / 64, (M + 127) / 128); }

extern "C" void kernel_launch(void* const* d_in, const int* in_sizes, int n_in,
                              void* d_out, int out_size) {
    (void)in_sizes; (void)n_in; (void)out_size;
    const int*   src    = (const int*)d_in[0];
    const int*   dst    = (const int*)d_in[1];
    const int*   etype  = (const int*)d_in[2];
    const int*   data   = (const int*)d_in[3];
    const int*   hisidx = (const int*)d_in[4];
    const int*   hislen = (const int*)d_in[5];
    const float* ent    = (const float*)d_in[6];
    const float* loopw  = (const float*)d_in[7];
    const float* rel    = (const float*)d_in[8];
    const float* absf   = (const float*)d_in[9];
    const float* absp   = (const float*)d_in[10];
    const float* cosfr  = (const float*)d_in[11];
    const float* cosph  = (const float*)d_in[12];
    const float* Wn     = (const float*)d_in[13];
    const float* Wsm    = (const float*)d_in[14];
    const float* W_ih   = (const float*)d_in[15];
    const float* W_hh   = (const float*)d_in[16];
    const float* b_ih   = (const float*)d_in[17];
    const float* b_hh   = (const float*)d_in[18];
    const float* Wb_w   = (const float*)d_in[19];
    const float* Wb_b   = (const float*)d_in[20];
    const float* Wc_w   = (const float*)d_in[21];
    const float* Wc_b   = (const float*)d_in[22];
    const float* Wd_w   = (const float*)d_in[23];
    const float* Wd_b   = (const float*)d_in[24];
    float* outp = (float*)d_out;

    float *prev, *hA, *hB, *pre, *gi, *gh, *reln, *cat, *cat600, *abuf, *qb;
    int* degp;
    void* p;
    cudaGetSymbolAddress(&p, g_prev);   prev   = (float*)p;
    cudaGetSymbolAddress(&p, g_hA);     hA     = (float*)p;
    cudaGetSymbolAddress(&p, g_hB);     hB     = (float*)p;
    cudaGetSymbolAddress(&p, g_pre);    pre    = (float*)p;
    cudaGetSymbolAddress(&p, g_gi);     gi     = (float*)p;
    cudaGetSymbolAddress(&p, g_gh);     gh     = (float*)p;
    cudaGetSymbolAddress(&p, g_reln);   reln   = (float*)p;
    cudaGetSymbolAddress(&p, g_cat);    cat    = (float*)p;
    cudaGetSymbolAddress(&p, g_cat600); cat600 = (float*)p;
    cudaGetSymbolAddress(&p, g_abuf);   abuf   = (float*)p;
    cudaGetSymbolAddress(&p, g_q);      qb     = (float*)p;
    cudaGetSymbolAddress(&p, g_deg);    degp   = (int*)p;

    const dim3 l2nBlk(32, 8);

    // rel_n = l2n(rel)
    l2n_kernel<<<(400 + 7) / 8, l2nBlk>>>(rel, reln, 400);
    // prev = l2n(ent @ loop_weight)
    sgemm_kernel<false, false, false, false><<<gemm_grid(H, NE), 256>>>(
        ent, H, loopw, H, nullptr, nullptr, nullptr, pre, H, NE, H, H);
    l2n_kernel<<<(NE + 7) / 8, l2nBlk>>>(pre, prev, NE);

    for (int i = 0; i < 3; i++) {
        cudaMemsetAsync(degp, 0, NE * sizeof(int), 0);
        count_kernel<<<(EE + 511) / 512, 512>>>(dst + i * EE);
        scan_kernel<<<1, 1024>>>();
        fill_kernel<<<(EE + 511) / 512, 512>>>(src + i * EE, dst + i * EE, etype + i * EE);
        gather1_kernel<<<NE, 64>>>();
        tebias_kernel<<<3, 256>>>(W_ih, b_ih, absf, absp, cosfr, cosph, (float)(2 - i));
        // layer 0: hB = relu(pre @ Wn[0] + hA @ Ws[0])
        gather2_kernel<<<NE, 64>>>(hA);
        sgemm_kernel<false, true, true, false><<<gemm_grid(H, NE), 256>>>(
            pre, H, Wn, H, hA, Wsm, nullptr, hB, H, NE, H, H);
        // layer 1: hA = relu(pre @ Wn[1] + hB @ Ws[1])
        gather2_kernel<<<NE, 64>>>(hB);
        sgemm_kernel<false, true, true, false><<<gemm_grid(H, NE), 256>>>(
            pre, H, Wn + H * H, H, hB, Wsm + H * H, nullptr, hA, H, NE, H, H);
        l2n_kernel<<<(NE + 7) / 8, l2nBlk>>>(hA, hA, NE);
        // GRU gates
        sgemm_kernel<true, false, false, false><<<gemm_grid(3 * H, NE), 256>>>(
            hA, H, W_ih, 248, nullptr, nullptr, nullptr, gi, 3 * H, NE, 3 * H, H);
        sgemm_kernel<true, false, false, false><<<gemm_grid(3 * H, NE), 256>>>(
            prev, H, W_hh, H, nullptr, nullptr, nullptr, gh, 3 * H, NE, 3 * H, H);
        gru_kernel<<<NE, 64>>>(b_hh);
    }

    // ---- phase 2: batch attention over histories ----
    tmp_kernel<<<dim3(NB, 3), 64>>>(hisidx, hislen);
    for (int k = 0; k < 3; k++) {
        cat_kernel<<<NB, 256>>>(k, (float)(2 - k), data, hislen, absf, absp, cosfr, cosph);
        sgemm_kernel<true, false, true, true><<<gemm_grid(H, NB), 256>>>(
            cat, 648, Wb_w, 648, nullptr, nullptr, Wb_b, abuf, H, NB, H, 648);
        atts_kernel<<<64, 256>>>(k, Wc_w, Wc_b);
    }
    combine_kernel<<<NB, 256>>>(data);
    sgemm_kernel<true, false, true, true><<<gemm_grid(H, NB), 256>>>(
        cat600, 600, Wd_w, 600, nullptr, nullptr, Wd_b, qb, H, NB, H, 600);
    // result = q @ out^T
    sgemm_kernel<true, false, false, false><<<gemm_grid(NE, NB), 256>>>(
        qb, H, prev, H, nullptr, nullptr, nullptr, outp, NE, NB, NE, H);
}

// round 13
// speedup vs baseline: 2.8371x; 1.4333x over previous
#include <cuda_runtime.h>
#include <math.h>
#include <stdint.h>

// ---------------- problem constants ----------------
constexpr int NE  = 20000;   // NUM_E
constexpr int H   = 200;
constexpr int EE  = 200000;  // E
constexpr int NB  = 512;     // BATCH
constexpr int TD  = 48;
constexpr int HDh = 24;      // TD/2

// ---------------- device scratch (no allocs allowed) ----------------
__device__ float g_prev[NE * H];
__device__ float g_hA[NE * H];
__device__ float g_hB[NE * H];
__device__ float g_pre[NE * H];
__device__ float g_relS[NE * H];
__device__ float g_gi[NE * 3 * H];
__device__ float g_gh[NE * 3 * H];
__device__ float g_reln[400 * H];
__device__ int   g_deg[NE];
__device__ int   g_rowptr[NE + 1];
__device__ int   g_cursor[NE];
__device__ int   g_esrc[EE];
__device__ int   g_erel[EE];
__device__ float g_biasP[3 * H];
__device__ float g_biasN[3 * H];
__device__ float g_sbuf[3][NB * H];
__device__ float g_cat[NB * 648];
__device__ float g_abuf[NB * H];
__device__ float g_atts[NB * 3];
__device__ float g_cat600[NB * 600];
__device__ float g_q[NB * H];

__device__ __forceinline__ float4 f4add(float4 a, float4 b) {
    return make_float4(a.x + b.x, a.y + b.y, a.z + b.z, a.w + b.w);
}
__device__ __forceinline__ float4 f4scale(float4 a, float s) {
    return make_float4(a.x * s, a.y * s, a.z * s, a.w * s);
}

// ---------------- TF32 tensor-core GEMM (mma.sync path; tcgen05 unavailable
// on this toolchain's compute_103 PTX target) ----------------
__device__ __forceinline__ uint32_t to_tf32(float x) {
    uint32_t r;
    asm("cvt.rna.tf32.f32 %0, %1;" : "=r"(r) : "f"(x));
    return r;
}

__device__ __forceinline__ void mma_tf32(float* d, const uint32_t* a, const uint32_t* b) {
    asm volatile(
        "mma.sync.aligned.m16n8k8.row.col.f32.tf32.tf32.f32 "
        "{%0,%1,%2,%3}, {%4,%5,%6,%7}, {%8,%9}, {%0,%1,%2,%3};"
        : "+f"(d[0]), "+f"(d[1]), "+f"(d[2]), "+f"(d[3])
        : "r"(a[0]), "r"(a[1]), "r"(a[2]), "r"(a[3]), "r"(b[0]), "r"(b[1]));
}

// swizzle: column ^ SW(k), SW(k) = ((k&3)^((k>>2)&3))&3) * 8
// - fragment reads (fixed k): constant XOR -> conflict-free
// - staging STS (fixed j, varying kg): kg-dependent XOR spreads banks -> conflict-free
__device__ __forceinline__ int swz(int k) { return (((k & 3) ^ ((k >> 2) & 3)) & 3) * 8; }

// C[M,N] = A[M,K] @ op(B) (+ A2 @ op(B2) if DUAL) (+ bias if BIAS), relu if RELU
// TRB: B stored [N, ldb], used transposed. Requirements: K, lda, ldb, N % 4 == 0;
// ldc, N even.
template <bool TRB, bool DUAL, bool RELU, bool BIAS>
__global__ void __launch_bounds__(256, 2) sgemm_kernel(
    const float* __restrict__ A, int lda,
    const float* __restrict__ B, int ldb,
    const float* __restrict__ A2, const float* __restrict__ B2,
    const float* __restrict__ bias,
    float* __restrict__ C, int ldc, int M, int N, int K) {
    constexpr int BM = 128, BN = 64, BK = 16;
    __shared__ uint32_t As[2][BK][BM];
    __shared__ uint32_t Bs[2][BK][BN];
    const int bm = blockIdx.y * BM;
    const int bn = blockIdx.x * BN;
    const int t  = threadIdx.x;
    const int lane = t & 31, warp = t >> 5;
    const int g = lane >> 2, tig = lane & 3;
    const int m0w = (warp & 3) * 32;
    const int n0w = (warp >> 2) * 32;

    // A staging: 128 rows x 4 kgroups = 512 float4 tasks (2 per thread)
    const int arow0 = t >> 2;          // task r=0: rows 0..63
    const int akg   = t & 3;
    // B staging TRB: 64 rows x 4 kg = 256 tasks (1 per thread)
    const int btrow = t >> 2;
    const int btkg  = t & 3;
    // B staging non-TRB: 16 k x 16 ngroups = 256 tasks
    const int bkk = t >> 4;
    const int bng = t & 15;

    const int ksteps = (K + BK - 1) / BK;
    const int nsteps = (DUAL ? 2 : 1) * ksteps;

    float acc[2][4][4] = {};
    float4 aR[2];
    float4 bR;
    aR[0] = aR[1] = bR = make_float4(0.f, 0.f, 0.f, 0.f);

    auto load_step = [&](int s) {
        int pass = DUAL ? (s >= ksteps ? 1 : 0) : 0;
        int k0 = (s - pass * ksteps) * BK;
        const float* Ap = pass ? A2 : A;
        const float* Bp = pass ? B2 : B;
#pragma unroll
        for (int r = 0; r < 2; r++) {
            int row = arow0 + r * 64;
            int gm = bm + row, gk = k0 + akg * 4;
            aR[r] = (gm < M && gk < K)
                        ? *(const float4*)(Ap + (size_t)gm * lda + gk)
                        : make_float4(0.f, 0.f, 0.f, 0.f);
        }
        if (TRB) {
            int gn = bn + btrow, gk = k0 + btkg * 4;
            bR = (gn < N && gk < K)
                     ? *(const float4*)(Bp + (size_t)gn * ldb + gk)
                     : make_float4(0.f, 0.f, 0.f, 0.f);
        } else {
            int gk = k0 + bkk, gn0 = bn + bng * 4;
            bR = (gk < K && gn0 < N)
                     ? *(const float4*)(Bp + (size_t)gk * ldb + gn0)
                     : make_float4(0.f, 0.f, 0.f, 0.f);
        }
    };

    auto store_smem = [&](int buf) {
#pragma unroll
        for (int r = 0; r < 2; r++) {
            int row = arow0 + r * 64;
            const float av[4] = {aR[r].x, aR[r].y, aR[r].z, aR[r].w};
#pragma unroll
            for (int j = 0; j < 4; j++) {
                int k = akg * 4 + j;
                As[buf][k][row ^ (((j ^ akg) & 3) * 8)] = to_tf32(av[j]);
            }
        }
        const float bv[4] = {bR.x, bR.y, bR.z, bR.w};
        if (TRB) {
#pragma unroll
            for (int j = 0; j < 4; j++) {
                int k = btkg * 4 + j;
                Bs[buf][k][btrow ^ (((j ^ btkg) & 3) * 8)] = to_tf32(bv[j]);
            }
        } else {
            int sw = swz(bkk);
#pragma unroll
            for (int j = 0; j < 4; j++) {
                Bs[buf][bkk][(bng * 4 + j) ^ sw] = to_tf32(bv[j]);
            }
        }
    };

    auto compute_sub = [&](int buf, int s) {
        const int k1 = tig + 8 * s;
        const int k2 = tig + 4 + 8 * s;
        const int sw1 = ((tig ^ (2 * s)) & 3) * 8;
        const int sw2 = ((tig ^ (2 * s + 1)) & 3) * 8;
        uint32_t a[2][4];
#pragma unroll
        for (int mt = 0; mt < 2; mt++) {
            int mb = m0w + mt * 16 + g;
            a[mt][0] = As[buf][k1][(mb    ) ^ sw1];
            a[mt][1] = As[buf][k1][(mb + 8) ^ sw1];
            a[mt][2] = As[buf][k2][(mb    ) ^ sw2];
            a[mt][3] = As[buf][k2][(mb + 8) ^ sw2];
        }
        uint32_t b[4][2];
#pragma unroll
        for (int nt = 0; nt < 4; nt++) {
            int nb = n0w + nt * 8 + g;
            b[nt][0] = Bs[buf][k1][nb ^ sw1];
            b[nt][1] = Bs[buf][k2][nb ^ sw2];
        }
#pragma unroll
        for (int mt = 0; mt < 2; mt++)
#pragma unroll
            for (int nt = 0; nt < 4; nt++)
                mma_tf32(acc[mt][nt], a[mt], b[nt]);
    };

    load_step(0);
    store_smem(0);
    __syncthreads();
    int buf = 0;
    for (int s = 1; s < nsteps; s++) {
        load_step(s);
        compute_sub(buf, 0);
        compute_sub(buf, 1);
        store_smem(buf ^ 1);
        __syncthreads();
        buf ^= 1;
    }
    compute_sub(buf, 0);
    compute_sub(buf, 1);

#pragma unroll
    for (int mt = 0; mt < 2; mt++) {
#pragma unroll
        for (int nt = 0; nt < 4; nt++) {
            int gm = bm + m0w + mt * 16 + g;
            int gn = bn + n0w + nt * 8 + 2 * tig;
            if (gn >= N) continue;
            float b0 = 0.f, b1 = 0.f;
            if (BIAS) { b0 = bias[gn]; b1 = bias[gn + 1]; }
            float v0 = acc[mt][nt][0] + b0, v1 = acc[mt][nt][1] + b1;
            float v2 = acc[mt][nt][2] + b0, v3 = acc[mt][nt][3] + b1;
            if (RELU) {
                v0 = fmaxf(v0, 0.f); v1 = fmaxf(v1, 0.f);
                v2 = fmaxf(v2, 0.f); v3 = fmaxf(v3, 0.f);
            }
            if (gm < M)     *(float2*)(C + (size_t)gm * ldc + gn)       = make_float2(v0, v1);
            if (gm + 8 < M) *(float2*)(C + (size_t)(gm + 8) * ldc + gn) = make_float2(v2, v3);
        }
    }
}

// ---------------- row L2 normalize (warp per row) ----------------
__global__ void l2n_kernel(const float* __restrict__ in, float* __restrict__ outp, int rows) {
    int r = blockIdx.x * blockDim.y + threadIdx.y;
    if (r >= rows) return;
    int lane = threadIdx.x;
    float s = 0.f;
    for (int c = lane; c < H; c += 32) { float v = in[r * H + c]; s += v * v; }
#pragma unroll
    for (int off = 16; off; off >>= 1) s += __shfl_xor_sync(0xffffffffu, s, off);
    float sc = 1.f / fmaxf(sqrtf(s), 1e-12f);
    for (int c = lane; c < H; c += 32) outp[r * H + c] = in[r * H + c] * sc;
}

// ---------------- CSR build ----------------
__global__ void count_kernel(const int* __restrict__ dsti) {
    int e = blockIdx.x * blockDim.x + threadIdx.x;
    if (e < EE) atomicAdd(&g_deg[dsti[e]], 1);
}

__global__ void scan_kernel() {
    __shared__ int s[1024];
    int t = threadIdx.x;
    int start = t * 20;
    int end = min(start + 20, NE);
    int local = 0;
    for (int i = start; i < end; i++) local += g_deg[i];
    s[t] = local;
    __syncthreads();
    for (int off = 1; off < 1024; off <<= 1) {
        int v = (t >= off) ? s[t - off] : 0;
        __syncthreads();
        s[t] += v;
        __syncthreads();
    }
    int run = s[t] - local;
    for (int i = start; i < end; i++) {
        g_rowptr[i] = run;
        g_cursor[i] = run;
        run += g_deg[i];
    }
    if (t == 1023) g_rowptr[NE] = run;
}

__global__ void fill_kernel(const int* __restrict__ srci, const int* __restrict__ dsti,
                            const int* __restrict__ eti) {
    int e = blockIdx.x * blockDim.x + threadIdx.x;
    if (e < EE) {
        int p = atomicAdd(&g_cursor[dsti[e]], 1);
        g_esrc[p] = srci[e];
        g_erel[p] = eti[e];
    }
}

// ---------------- vectorized CSR gathers ----------------
__global__ void __launch_bounds__(64) gather1_kernel() {
    int n = blockIdx.x;
    int t = threadIdx.x;
    int b0 = g_rowptr[n], e0 = g_rowptr[n + 1];
    int c = t * 4;
    float4 s1 = make_float4(0.f, 0.f, 0.f, 0.f);
    float4 s2 = make_float4(0.f, 0.f, 0.f, 0.f);
    if (t < 50) {
        int i = b0;
        for (; i + 4 <= e0; i += 4) {
            int a0 = g_esrc[i], a1 = g_esrc[i + 1], a2 = g_esrc[i + 2], a3 = g_esrc[i + 3];
            int r0 = g_erel[i], r1 = g_erel[i + 1], r2 = g_erel[i + 2], r3 = g_erel[i + 3];
            float4 v0 = *(const float4*)(g_prev + a0 * H + c);
            float4 v1 = *(const float4*)(g_prev + a1 * H + c);
            float4 v2 = *(const float4*)(g_prev + a2 * H + c);
            float4 v3 = *(const float4*)(g_prev + a3 * H + c);
            float4 w0 = *(const float4*)(g_reln + r0 * H + c);
            float4 w1 = *(const float4*)(g_reln + r1 * H + c);
            float4 w2 = *(const float4*)(g_reln + r2 * H + c);
            float4 w3 = *(const float4*)(g_reln + r3 * H + c);
            s1 = f4add(f4add(f4add(f4add(s1, v0), v1), v2), v3);
            s2 = f4add(f4add(f4add(f4add(s2, w0), w1), w2), w3);
        }
        for (; i < e0; i++) {
            s1 = f4add(s1, *(const float4*)(g_prev + g_esrc[i] * H + c));
            s2 = f4add(s2, *(const float4*)(g_reln + g_erel[i] * H + c));
        }
    }
    float inv = 1.f / fmaxf((float)(e0 - b0), 1.f);
    float4 v = f4scale(s1, inv);
    float ss = v.x * v.x + v.y * v.y + v.z * v.z + v.w * v.w;
#pragma unroll
    for (int off = 16; off; off >>= 1) ss += __shfl_xor_sync(0xffffffffu, ss, off);
    __shared__ float red[2];
    if ((t & 31) == 0) red[t >> 5] = ss;
    __syncthreads();
    float sc = 1.f / fmaxf(sqrtf(red[0] + red[1]), 1e-12f);
    if (t < 50) {
        *(float4*)(g_hA + n * H + c) = f4scale(v, sc);
        *(float4*)(g_relS + n * H + c) = s2;
    }
}

__global__ void __launch_bounds__(64) gather2_kernel(const float* __restrict__ hsrc) {
    int n = blockIdx.x;
    int t = threadIdx.x;
    if (t >= 50) return;
    int c = t * 4;
    int b0 = g_rowptr[n], e0 = g_rowptr[n + 1];
    float4 s = make_float4(0.f, 0.f, 0.f, 0.f);
    int i = b0;
    for (; i + 4 <= e0; i += 4) {
        int a0 = g_esrc[i], a1 = g_esrc[i + 1], a2 = g_esrc[i + 2], a3 = g_esrc[i + 3];
        float4 v0 = *(const float4*)(hsrc + a0 * H + c);
        float4 v1 = *(const float4*)(hsrc + a1 * H + c);
        float4 v2 = *(const float4*)(hsrc + a2 * H + c);
        float4 v3 = *(const float4*)(hsrc + a3 * H + c);
        s = f4add(f4add(f4add(f4add(s, v0), v1), v2), v3);
    }
    for (; i < e0; i++) s = f4add(s, *(const float4*)(hsrc + g_esrc[i] * H + c));
    float inv = 1.f / fmaxf((float)(e0 - b0), 1.f);
    float4 r = *(const float4*)(g_relS + n * H + c);
    *(float4*)(g_pre + n * H + c) = f4scale(f4add(s, r), inv);
}

// ---------------- time-encoding bias ----------------
__global__ void tebias_kernel(const float* __restrict__ W_ih, const float* __restrict__ b_ih,
                              const float* __restrict__ af, const float* __restrict__ ap,
                              const float* __restrict__ cf, const float* __restrict__ cp,
                              float tpos) {
    int j = blockIdx.x * blockDim.x + threadIdx.x;
    if (j >= 3 * H) return;
    float sp = b_ih[j], sn = b_ih[j];
    for (int d = 0; d < TD; d++) {
        float tep, ten;
        if (d < HDh) {
            tep = tanhf((tpos + 1.f) * af[d] + ap[d]);
            ten = tanhf(101.f * af[d] + ap[d]);
        } else {
            tep = cosf(tpos * cf[d - HDh] + cp[d - HDh]);
            ten = cosf(100.f * cf[d - HDh] + cp[d - HDh]);
        }
        float w = W_ih[j * 248 + 200 + d];
        sp += w * tep;
        sn += w * ten;
    }
    g_biasP[j] = sp;
    g_biasN[j] = sn;
}

// ---------------- GRU update + l2n (vectorized, 64 threads/node) ----------------
__global__ void __launch_bounds__(64) gru_kernel(const float* __restrict__ b_hh) {
    int n = blockIdx.x;
    int t = threadIdx.x;
    int c = t * 4;
    const float* bp = (g_deg[n] > 0) ? g_biasP : g_biasN;
    float4 v = make_float4(0.f, 0.f, 0.f, 0.f);
    if (t < 50) {
        float4 ir = *(const float4*)(g_gi + n * 600 + c);
        float4 iz = *(const float4*)(g_gi + n * 600 + 200 + c);
        float4 in_ = *(const float4*)(g_gi + n * 600 + 400 + c);
        float4 hr = *(const float4*)(g_gh + n * 600 + c);
        float4 hz = *(const float4*)(g_gh + n * 600 + 200 + c);
        float4 hn = *(const float4*)(g_gh + n * 600 + 400 + c);
        float4 pv = *(const float4*)(g_prev + n * H + c);
        float4 bp0 = *(const float4*)(bp + c);
        float4 bp1 = *(const float4*)(bp + 200 + c);
        float4 bp2 = *(const float4*)(bp + 400 + c);
        float4 bh0 = *(const float4*)(b_hh + c);
        float4 bh1 = *(const float4*)(b_hh + 200 + c);
        float4 bh2 = *(const float4*)(b_hh + 400 + c);
        float* vv = (float*)&v;
        const float *irp = (const float*)&ir, *izp = (const float*)&iz, *inp = (const float*)&in_;
        const float *hrp = (const float*)&hr, *hzp = (const float*)&hz, *hnp = (const float*)&hn;
        const float *pvp = (const float*)&pv;
        const float *b0p = (const float*)&bp0, *b1p = (const float*)&bp1, *b2p = (const float*)&bp2;
        const float *c0p = (const float*)&bh0, *c1p = (const float*)&bh1, *c2p = (const float*)&bh2;
#pragma unroll
        for (int j = 0; j < 4; j++) {
            float rsum = irp[j] + b0p[j] + hrp[j] + c0p[j];
            float zsum = izp[j] + b1p[j] + hzp[j] + c1p[j];
            float hnv  = hnp[j] + c2p[j];
            float rg = 1.f / (1.f + expf(-rsum));
            float zg = 1.f / (1.f + expf(-zsum));
            float ng = tanhf(inp[j] + b2p[j] + rg * hnv);
            vv[j] = (1.f - zg) * ng + zg * pvp[j];
        }
    }
    float ss = v.x * v.x + v.y * v.y + v.z * v.z + v.w * v.w;
#pragma unroll
    for (int off = 16; off; off >>= 1) ss += __shfl_xor_sync(0xffffffffu, ss, off);
    __shared__ float red[2];
    if ((t & 31) == 0) red[t >> 5] = ss;
    __syncthreads();
    float sc = 1.f / fmaxf(sqrtf(red[0] + red[1]), 1e-12f);
    if (t < 50) *(float4*)(g_prev + n * H + c) = f4scale(v, sc);
}

// ---------------- phase 2: history summaries (vectorized) ----------------
__global__ void __launch_bounds__(64) tmp_kernel(const int* __restrict__ his_idx,
                                                 const int* __restrict__ his_len) {
    int b = blockIdx.x, k = blockIdx.y;
    int t = threadIdx.x;
    int c = t * 4;
    int ln = his_len[b * 3 + k];
    const int* idxp = his_idx + (b * 3 + k) * 32;
    float4 s = make_float4(0.f, 0.f, 0.f, 0.f);
    if (t < 50) {
        int l = 0;
        for (; l + 4 <= ln; l += 4) {
            int a0 = idxp[l], a1 = idxp[l + 1], a2 = idxp[l + 2], a3 = idxp[l + 3];
            float4 v0 = *(const float4*)(g_prev + a0 * H + c);
            float4 v1 = *(const float4*)(g_prev + a1 * H + c);
            float4 v2 = *(const float4*)(g_prev + a2 * H + c);
            float4 v3 = *(const float4*)(g_prev + a3 * H + c);
            s = f4add(f4add(f4add(f4add(s, v0), v1), v2), v3);
        }
        for (; l < ln; l++) s = f4add(s, *(const float4*)(g_prev + idxp[l] * H + c));
    }
    float4 v = f4scale(s, 1.f / fmaxf((float)ln, 1.f));
    float ss = v.x * v.x + v.y * v.y + v.z * v.z + v.w * v.w;
#pragma unroll
    for (int off = 16; off; off >>= 1) ss += __shfl_xor_sync(0xffffffffu, ss, off);
    __shared__ float red[2];
    if ((t & 31) == 0) red[t >> 5] = ss;
    __syncthreads();
    float sc = 1.f / fmaxf(sqrtf(red[0] + red[1]), 1e-12f);
    if (t < 50) *(float4*)(&g_sbuf[k][b * H + c]) = f4scale(v, sc);
}

__global__ void cat_kernel(int k, float timk, const int* __restrict__ data,
                           const int* __restrict__ his_len,
                           const float* __restrict__ af, const float* __restrict__ ap,
                           const float* __restrict__ cf, const float* __restrict__ cp) {
    int b = blockIdx.x, c = threadIdx.x;
    int si = data[b * 4 + 0], ri = data[b * 4 + 1];
    if (c < H) {
        g_cat[b * 648 + c]       = g_prev[si * H + c];
        g_cat[b * 648 + 200 + c] = g_reln[ri * H + c];
        g_cat[b * 648 + 400 + c] = g_sbuf[k][b * H + c];
    }
    if (c < TD) {
        int ln = his_len[b * 3 + k];
        float t = (ln > 0) ? timk : 100.f;
        float v = (c < HDh) ? tanhf((t + 1.f) * af[c] + ap[c])
                            : cosf(t * cf[c - HDh] + cp[c - HDh]);
        g_cat[b * 648 + 600 + c] = v;
    }
}

__global__ void atts_kernel(int k, const float* __restrict__ Wc_w, const float* __restrict__ Wc_b) {
    int warp = (blockIdx.x * blockDim.x + threadIdx.x) >> 5;
    int lane = threadIdx.x & 31;
    if (warp >= NB) return;
    float s = 0.f;
    for (int c = lane; c < H; c += 32) s += g_abuf[warp * H + c] * Wc_w[c];
#pragma unroll
    for (int off = 16; off; off >>= 1) s += __shfl_xor_sync(0xffffffffu, s, off);
    if (lane == 0) g_atts[warp * 3 + k] = s + Wc_b[0];
}

__global__ void combine_kernel(const int* __restrict__ data) {
    int b = blockIdx.x, c = threadIdx.x;
    float a0 = g_atts[b * 3 + 0], a1 = g_atts[b * 3 + 1], a2 = g_atts[b * 3 + 2];
    float m = fmaxf(a0, fmaxf(a1, a2));
    float e0 = expf(a0 - m), e1 = expf(a1 - m), e2 = expf(a2 - m);
    float inv = 1.f / (e0 + e1 + e2);
    if (c < H) {
        int si = data[b * 4 + 0], ri = data[b * 4 + 1];
        float o2 = (e0 * g_sbuf[0][b * H + c] + e1 * g_sbuf[1][b * H + c] +
                    e2 * g_sbuf[2][b * H + c]) * inv;
        g_cat600[b * 600 + c]       = g_prev[si * H + c];
        g_cat600[b * 600 + 200 + c] = g_reln[ri * H + c];
        g_cat600[b * 600 + 400 + c] = o2;
    }
}

// ---------------- host orchestration ----------------
static inline dim3 gemm_grid(int N, int M) { return dim3((N + 63) / 64, (M + 127) / 128); }

extern "C" void kernel_launch(void* const* d_in, const int* in_sizes, int n_in,
                              void* d_out, int out_size) {
    (void)in_sizes; (void)n_in; (void)out_size;
    const int*   src    = (const int*)d_in[0];
    const int*   dst    = (const int*)d_in[1];
    const int*   etype  = (const int*)d_in[2];
    const int*   data   = (const int*)d_in[3];
    const int*   hisidx = (const int*)d_in[4];
    const int*   hislen = (const int*)d_in[5];
    const float* ent    = (const float*)d_in[6];
    const float* loopw  = (const float*)d_in[7];
    const float* rel    = (const float*)d_in[8];
    const float* absf   = (const float*)d_in[9];
    const float* absp   = (const float*)d_in[10];
    const float* cosfr  = (const float*)d_in[11];
    const float* cosph  = (const float*)d_in[12];
    const float* Wn     = (const float*)d_in[13];
    const float* Wsm    = (const float*)d_in[14];
    const float* W_ih   = (const float*)d_in[15];
    const float* W_hh   = (const float*)d_in[16];
    const float* b_ih   = (const float*)d_in[17];
    const float* b_hh   = (const float*)d_in[18];
    const float* Wb_w   = (const float*)d_in[19];
    const float* Wb_b   = (const float*)d_in[20];
    const float* Wc_w   = (const float*)d_in[21];
    const float* Wc_b   = (const float*)d_in[22];
    const float* Wd_w   = (const float*)d_in[23];
    const float* Wd_b   = (const float*)d_in[24];
    float* outp = (float*)d_out;

    float *prev, *hA, *hB, *pre, *gi, *gh, *reln, *cat, *cat600, *abuf, *qb;
    int* degp;
    void* p;
    cudaGetSymbolAddress(&p, g_prev);   prev   = (float*)p;
    cudaGetSymbolAddress(&p, g_hA);     hA     = (float*)p;
    cudaGetSymbolAddress(&p, g_hB);     hB     = (float*)p;
    cudaGetSymbolAddress(&p, g_pre);    pre    = (float*)p;
    cudaGetSymbolAddress(&p, g_gi);     gi     = (float*)p;
    cudaGetSymbolAddress(&p, g_gh);     gh     = (float*)p;
    cudaGetSymbolAddress(&p, g_reln);   reln   = (float*)p;
    cudaGetSymbolAddress(&p, g_cat);    cat    = (float*)p;
    cudaGetSymbolAddress(&p, g_cat600); cat600 = (float*)p;
    cudaGetSymbolAddress(&p, g_abuf);   abuf   = (float*)p;
    cudaGetSymbolAddress(&p, g_q);      qb     = (float*)p;
    cudaGetSymbolAddress(&p, g_deg);    degp   = (int*)p;

    const dim3 l2nBlk(32, 8);

    // rel_n = l2n(rel)
    l2n_kernel<<<(400 + 7) / 8, l2nBlk>>>(rel, reln, 400);
    // prev = l2n(ent @ loop_weight)
    sgemm_kernel<false, false, false, false><<<gemm_grid(H, NE), 256>>>(
        ent, H, loopw, H, nullptr, nullptr, nullptr, pre, H, NE, H, H);
    l2n_kernel<<<(NE + 7) / 8, l2nBlk>>>(pre, prev, NE);

    for (int i = 0; i < 3; i++) {
        cudaMemsetAsync(degp, 0, NE * sizeof(int), 0);
        count_kernel<<<(EE + 511) / 512, 512>>>(dst + i * EE);
        scan_kernel<<<1, 1024>>>();
        fill_kernel<<<(EE + 511) / 512, 512>>>(src + i * EE, dst + i * EE, etype + i * EE);
        gather1_kernel<<<NE, 64>>>();
        tebias_kernel<<<3, 256>>>(W_ih, b_ih, absf, absp, cosfr, cosph, (float)(2 - i));
        // layer 0: hB = relu(pre @ Wn[0] + hA @ Ws[0])
        gather2_kernel<<<NE, 64>>>(hA);
        sgemm_kernel<false, true, true, false><<<gemm_grid(H, NE), 256>>>(
            pre, H, Wn, H, hA, Wsm, nullptr, hB, H, NE, H, H);
        // layer 1: hA = relu(pre @ Wn[1] + hB @ Ws[1])
        gather2_kernel<<<NE, 64>>>(hB);
        sgemm_kernel<false, true, true, false><<<gemm_grid(H, NE), 256>>>(
            pre, H, Wn + H * H, H, hB, Wsm + H * H, nullptr, hA, H, NE, H, H);
        l2n_kernel<<<(NE + 7) / 8, l2nBlk>>>(hA, hA, NE);
        // GRU gates
        sgemm_kernel<true, false, false, false><<<gemm_grid(3 * H, NE), 256>>>(
            hA, H, W_ih, 248, nullptr, nullptr, nullptr, gi, 3 * H, NE, 3 * H, H);
        sgemm_kernel<true, false, false, false><<<gemm_grid(3 * H, NE), 256>>>(
            prev, H, W_hh, H, nullptr, nullptr, nullptr, gh, 3 * H, NE, 3 * H, H);
        gru_kernel<<<NE, 64>>>(b_hh);
    }

    // ---- phase 2: batch attention over histories ----
    tmp_kernel<<<dim3(NB, 3), 64>>>(hisidx, hislen);
    for (int k = 0; k < 3; k++) {
        cat_kernel<<<NB, 256>>>(k, (float)(2 - k), data, hislen, absf, absp, cosfr, cosph);
        sgemm_kernel<true, false, true, true><<<gemm_grid(H, NB), 256>>>(
            cat, 648, Wb_w, 648, nullptr, nullptr, Wb_b, abuf, H, NB, H, 648);
        atts_kernel<<<64, 256>>>(k, Wc_w, Wc_b);
    }
    combine_kernel<<<NB, 256>>>(data);
    sgemm_kernel<true, false, true, true><<<gemm_grid(H, NB), 256>>>(
        cat600, 600, Wd_w, 600, nullptr, nullptr, Wd_b, qb, H, NB, H, 600);
    // result = q @ out^T
    sgemm_kernel<true, false, false, false><<<gemm_grid(NE, NB), 256>>>(
        qb, H, prev, H, nullptr, nullptr, nullptr, outp, NE, NB, NE, H);
}

// round 15
// speedup vs baseline: 3.2060x; 1.1300x over previous
#include <cuda_runtime.h>
#include <math.h>
#include <stdint.h>

// ---------------- problem constants ----------------
constexpr int NE  = 20000;   // NUM_E
constexpr int H   = 200;
constexpr int EE  = 200000;  // E
constexpr int NB  = 512;     // BATCH
constexpr int TD  = 48;
constexpr int HDh = 24;      // TD/2

// ---------------- device scratch (no allocs allowed) ----------------
__device__ float g_prev[NE * H];
__device__ float g_hA[NE * H];
__device__ float g_hB[NE * H];
__device__ float g_pre[NE * H];
__device__ float g_relS[NE * H];
__device__ float g_gi[NE * 3 * H];
__device__ float g_gh[NE * 3 * H];
__device__ float g_reln[400 * H];
__device__ int   g_deg[NE];
__device__ int   g_rowptr[NE + 1];
__device__ int   g_cursor[NE];
__device__ int   g_esrc[EE];
__device__ int   g_erel[EE];
__device__ float g_biasP[3 * H];
__device__ float g_biasN[3 * H];
__device__ float g_sbuf[3][NB * H];
__device__ float g_cat[NB * 648];
__device__ float g_abuf[NB * H];
__device__ float g_atts[NB * 3];
__device__ float g_cat600[NB * 600];
__device__ float g_q[NB * H];
// transposed square weights: [0]=loopw^T, [1..2]=Wn^T, [3..4]=Ws^T
__device__ float g_WT[5 * H * H];

__device__ __forceinline__ float4 f4add(float4 a, float4 b) {
    return make_float4(a.x + b.x, a.y + b.y, a.z + b.z, a.w + b.w);
}
__device__ __forceinline__ float4 f4scale(float4 a, float s) {
    return make_float4(a.x * s, a.y * s, a.z * s, a.w * s);
}

// ---------------- TF32 tensor-core GEMM (mma.sync + cp.async pipeline) ----------------
__device__ __forceinline__ uint32_t to_tf32(float x) {
    uint32_t r;
    asm("cvt.rna.tf32.f32 %0, %1;" : "=r"(r) : "f"(x));
    return r;
}

__device__ __forceinline__ void mma_tf32(float* d, const uint32_t* a, const uint32_t* b) {
    asm volatile(
        "mma.sync.aligned.m16n8k8.row.col.f32.tf32.tf32.f32 "
        "{%0,%1,%2,%3}, {%4,%5,%6,%7}, {%8,%9}, {%0,%1,%2,%3};"
        : "+f"(d[0]), "+f"(d[1]), "+f"(d[2]), "+f"(d[3])
        : "r"(a[0]), "r"(a[1]), "r"(a[2]), "r"(a[3]), "r"(b[0]), "r"(b[1]));
}

__device__ __forceinline__ void cp16(void* smem, const void* g, bool v) {
    uint32_t sa = (uint32_t)__cvta_generic_to_shared(smem);
    int sz = v ? 16 : 0;
    asm volatile("cp.async.cg.shared.global [%0], [%1], 16, %2;"
                 :: "r"(sa), "l"(g), "r"(sz) : "memory");
}
#define CP_COMMIT() asm volatile("cp.async.commit_group;" ::: "memory")
#define CP_WAIT1()  asm volatile("cp.async.wait_group 1;" ::: "memory")

// C[M,N] = A[M,K] @ B^T (+ A2 @ B2^T if DUAL) (+ bias if BIAS), relu if RELU
// A: [M, lda] row-major (K contiguous). B: [N, ldb] row-major (K contiguous).
// Requirements: lda, ldb % 4 == 0; ldc, N even. OOB K/M/N zero-filled.
template <bool DUAL, bool RELU, bool BIAS>
__global__ void __launch_bounds__(256, 2) sgemm_kernel(
    const float* __restrict__ A, int lda,
    const float* __restrict__ B, int ldb,
    const float* __restrict__ A2, const float* __restrict__ B2,
    const float* __restrict__ bias,
    float* __restrict__ C, int ldc, int M, int N, int K) {
    constexpr int BM = 128, BN = 64, BK = 16, ST = 3;
    // [row][16 k] raw f32, 16B-chunk swizzle: chunk' = chunk ^ ((row>>1)&3)
    __shared__ float As[ST][BM][BK];
    __shared__ float Bs[ST][BN][BK];
    const int bm = blockIdx.y * BM;
    const int bn = blockIdx.x * BN;
    const int t  = threadIdx.x;
    const int lane = t & 31, warp = t >> 5;
    const int g = lane >> 2, tig = lane & 3;
    const int m0w = (warp & 3) * 32;
    const int n0w = (warp >> 2) * 32;

    const int ksteps = (K + BK - 1) / BK;
    const int nsteps = (DUAL ? 2 : 1) * ksteps;

    float acc[2][4][4] = {};

    const int chunk = t & 3;       // staging chunk (4 k each)
    const int srow  = t >> 2;      // staging row base

    auto issue = [&](int s) {
        if (s >= nsteps) return;
        int pass = DUAL ? (s >= ksteps ? 1 : 0) : 0;
        int k0 = (s - pass * ksteps) * BK;
        const float* Ap = pass ? A2 : A;
        const float* Bp = pass ? B2 : B;
        int buf = s % ST;
        int gk = k0 + chunk * 4;
        bool kok = gk < K;
#pragma unroll
        for (int r = 0; r < 2; r++) {
            int m = srow + r * 64;
            int gm = bm + m;
            float* dst = &As[buf][m][(chunk ^ ((m >> 1) & 3)) << 2];
            cp16(dst, Ap + (size_t)gm * lda + gk, (gm < M) && kok);
        }
        {
            int gn = bn + srow;
            float* dst = &Bs[buf][srow][(chunk ^ ((srow >> 1) & 3)) << 2];
            cp16(dst, Bp + (size_t)gn * ldb + gk, (gn < N) && kok);
        }
    };

    auto compute_sub = [&](int buf, int sub) {
        const int c1 = 2 * sub, c2 = 2 * sub + 1;
        uint32_t a[2][4];
#pragma unroll
        for (int mt = 0; mt < 2; mt++) {
            int mb = m0w + mt * 16 + g;
            int sw = (mb >> 1) & 3;     // same for mb and mb+8
            a[mt][0] = to_tf32(As[buf][mb    ][((c1 ^ sw) << 2) | tig]);
            a[mt][1] = to_tf32(As[buf][mb + 8][((c1 ^ sw) << 2) | tig]);
            a[mt][2] = to_tf32(As[buf][mb    ][((c2 ^ sw) << 2) | tig]);
            a[mt][3] = to_tf32(As[buf][mb + 8][((c2 ^ sw) << 2) | tig]);
        }
        uint32_t b[4][2];
#pragma unroll
        for (int nt = 0; nt < 4; nt++) {
            int nb = n0w + nt * 8 + g;
            int sw = (nb >> 1) & 3;
            b[nt][0] = to_tf32(Bs[buf][nb][((c1 ^ sw) << 2) | tig]);
            b[nt][1] = to_tf32(Bs[buf][nb][((c2 ^ sw) << 2) | tig]);
        }
#pragma unroll
        for (int mt = 0; mt < 2; mt++)
#pragma unroll
            for (int nt = 0; nt < 4; nt++)
                mma_tf32(acc[mt][nt], a[mt], b[nt]);
    };

    issue(0); CP_COMMIT();
    issue(1); CP_COMMIT();
    for (int s = 0; s < nsteps; s++) {
        CP_WAIT1();
        __syncthreads();
        issue(s + 2); CP_COMMIT();
        int buf = s % ST;
        compute_sub(buf, 0);
        compute_sub(buf, 1);
    }

#pragma unroll
    for (int mt = 0; mt < 2; mt++) {
#pragma unroll
        for (int nt = 0; nt < 4; nt++) {
            int gm = bm + m0w + mt * 16 + g;
            int gn = bn + n0w + nt * 8 + 2 * tig;
            if (gn >= N) continue;
            float b0 = 0.f, b1 = 0.f;
            if (BIAS) { b0 = bias[gn]; b1 = bias[gn + 1]; }
            float v0 = acc[mt][nt][0] + b0, v1 = acc[mt][nt][1] + b1;
            float v2 = acc[mt][nt][2] + b0, v3 = acc[mt][nt][3] + b1;
            if (RELU) {
                v0 = fmaxf(v0, 0.f); v1 = fmaxf(v1, 0.f);
                v2 = fmaxf(v2, 0.f); v3 = fmaxf(v3, 0.f);
            }
            if (gm < M)     *(float2*)(C + (size_t)gm * ldc + gn)       = make_float2(v0, v1);
            if (gm + 8 < M) *(float2*)(C + (size_t)(gm + 8) * ldc + gn) = make_float2(v2, v3);
        }
    }
}

// ---------------- transpose (for square weight matrices) ----------------
__global__ void transpose_kernel(const float* __restrict__ in, float* __restrict__ outp,
                                 int rows, int cols) {
    __shared__ float tile[32][33];
    int x = blockIdx.x * 32 + threadIdx.x;
    int y = blockIdx.y * 32 + threadIdx.y;
    if (x < cols && y < rows) tile[threadIdx.y][threadIdx.x] = in[y * cols + x];
    __syncthreads();
    int ox = blockIdx.y * 32 + threadIdx.x;   // new col = old row
    int oy = blockIdx.x * 32 + threadIdx.y;   // new row = old col
    if (ox < rows && oy < cols) outp[oy * rows + ox] = tile[threadIdx.x][threadIdx.y];
}

// ---------------- row L2 normalize (warp per row) ----------------
__global__ void l2n_kernel(const float* __restrict__ in, float* __restrict__ outp, int rows) {
    int r = blockIdx.x * blockDim.y + threadIdx.y;
    if (r >= rows) return;
    int lane = threadIdx.x;
    float s = 0.f;
    for (int c = lane; c < H; c += 32) { float v = in[r * H + c]; s += v * v; }
#pragma unroll
    for (int off = 16; off; off >>= 1) s += __shfl_xor_sync(0xffffffffu, s, off);
    float sc = 1.f / fmaxf(sqrtf(s), 1e-12f);
    for (int c = lane; c < H; c += 32) outp[r * H + c] = in[r * H + c] * sc;
}

// ---------------- CSR build ----------------
__global__ void count_kernel(const int* __restrict__ dsti) {
    int e = blockIdx.x * blockDim.x + threadIdx.x;
    if (e < EE) atomicAdd(&g_deg[dsti[e]], 1);
}

__global__ void scan_kernel() {
    __shared__ int s[1024];
    int t = threadIdx.x;
    int start = t * 20;
    int end = min(start + 20, NE);
    int local = 0;
    for (int i = start; i < end; i++) local += g_deg[i];
    s[t] = local;
    __syncthreads();
    for (int off = 1; off < 1024; off <<= 1) {
        int v = (t >= off) ? s[t - off] : 0;
        __syncthreads();
        s[t] += v;
        __syncthreads();
    }
    int run = s[t] - local;
    for (int i = start; i < end; i++) {
        g_rowptr[i] = run;
        g_cursor[i] = run;
        run += g_deg[i];
    }
    if (t == 1023) g_rowptr[NE] = run;
}

__global__ void fill_kernel(const int* __restrict__ srci, const int* __restrict__ dsti,
                            const int* __restrict__ eti) {
    int e = blockIdx.x * blockDim.x + threadIdx.x;
    if (e < EE) {
        int p = atomicAdd(&g_cursor[dsti[e]], 1);
        g_esrc[p] = srci[e];
        g_erel[p] = eti[e];
    }
}

// ---------------- vectorized CSR gathers ----------------
__global__ void __launch_bounds__(64) gather1_kernel() {
    int n = blockIdx.x;
    int t = threadIdx.x;
    int b0 = g_rowptr[n], e0 = g_rowptr[n + 1];
    int c = t * 4;
    float4 s1 = make_float4(0.f, 0.f, 0.f, 0.f);
    float4 s2 = make_float4(0.f, 0.f, 0.f, 0.f);
    if (t < 50) {
        int i = b0;
        for (; i + 4 <= e0; i += 4) {
            int a0 = g_esrc[i], a1 = g_esrc[i + 1], a2 = g_esrc[i + 2], a3 = g_esrc[i + 3];
            int r0 = g_erel[i], r1 = g_erel[i + 1], r2 = g_erel[i + 2], r3 = g_erel[i + 3];
            float4 v0 = *(const float4*)(g_prev + a0 * H + c);
            float4 v1 = *(const float4*)(g_prev + a1 * H + c);
            float4 v2 = *(const float4*)(g_prev + a2 * H + c);
            float4 v3 = *(const float4*)(g_prev + a3 * H + c);
            float4 w0 = *(const float4*)(g_reln + r0 * H + c);
            float4 w1 = *(const float4*)(g_reln + r1 * H + c);
            float4 w2 = *(const float4*)(g_reln + r2 * H + c);
            float4 w3 = *(const float4*)(g_reln + r3 * H + c);
            s1 = f4add(f4add(f4add(f4add(s1, v0), v1), v2), v3);
            s2 = f4add(f4add(f4add(f4add(s2, w0), w1), w2), w3);
        }
        for (; i < e0; i++) {
            s1 = f4add(s1, *(const float4*)(g_prev + g_esrc[i] * H + c));
            s2 = f4add(s2, *(const float4*)(g_reln + g_erel[i] * H + c));
        }
    }
    float inv = 1.f / fmaxf((float)(e0 - b0), 1.f);
    float4 v = f4scale(s1, inv);
    float ss = v.x * v.x + v.y * v.y + v.z * v.z + v.w * v.w;
#pragma unroll
    for (int off = 16; off; off >>= 1) ss += __shfl_xor_sync(0xffffffffu, ss, off);
    __shared__ float red[2];
    if ((t & 31) == 0) red[t >> 5] = ss;
    __syncthreads();
    float sc = 1.f / fmaxf(sqrtf(red[0] + red[1]), 1e-12f);
    if (t < 50) {
        *(float4*)(g_hA + n * H + c) = f4scale(v, sc);
        *(float4*)(g_relS + n * H + c) = s2;
    }
}

__global__ void __launch_bounds__(64) gather2_kernel(const float* __restrict__ hsrc) {
    int n = blockIdx.x;
    int t = threadIdx.x;
    if (t >= 50) return;
    int c = t * 4;
    int b0 = g_rowptr[n], e0 = g_rowptr[n + 1];
    float4 s = make_float4(0.f, 0.f, 0.f, 0.f);
    int i = b0;
    for (; i + 4 <= e0; i += 4) {
        int a0 = g_esrc[i], a1 = g_esrc[i + 1], a2 = g_esrc[i + 2], a3 = g_esrc[i + 3];
        float4 v0 = *(const float4*)(hsrc + a0 * H + c);
        float4 v1 = *(const float4*)(hsrc + a1 * H + c);
        float4 v2 = *(const float4*)(hsrc + a2 * H + c);
        float4 v3 = *(const float4*)(hsrc + a3 * H + c);
        s = f4add(f4add(f4add(f4add(s, v0), v1), v2), v3);
    }
    for (; i < e0; i++) s = f4add(s, *(const float4*)(hsrc + g_esrc[i] * H + c));
    float inv = 1.f / fmaxf((float)(e0 - b0), 1.f);
    float4 r = *(const float4*)(g_relS + n * H + c);
    *(float4*)(g_pre + n * H + c) = f4scale(f4add(s, r), inv);
}

// ---------------- time-encoding bias ----------------
__global__ void tebias_kernel(const float* __restrict__ W_ih, const float* __restrict__ b_ih,
                              const float* __restrict__ af, const float* __restrict__ ap,
                              const float* __restrict__ cf, const float* __restrict__ cp,
                              float tpos) {
    int j = blockIdx.x * blockDim.x + threadIdx.x;
    if (j >= 3 * H) return;
    float sp = b_ih[j], sn = b_ih[j];
    for (int d = 0; d < TD; d++) {
        float tep, ten;
        if (d < HDh) {
            tep = tanhf((tpos + 1.f) * af[d] + ap[d]);
            ten = tanhf(101.f * af[d] + ap[d]);
        } else {
            tep = cosf(tpos * cf[d - HDh] + cp[d - HDh]);
            ten = cosf(100.f * cf[d - HDh] + cp[d - HDh]);
        }
        float w = W_ih[j * 248 + 200 + d];
        sp += w * tep;
        sn += w * ten;
    }
    g_biasP[j] = sp;
    g_biasN[j] = sn;
}

// ---------------- GRU update + l2n (vectorized, 64 threads/node) ----------------
__global__ void __launch_bounds__(64) gru_kernel(const float* __restrict__ b_hh) {
    int n = blockIdx.x;
    int t = threadIdx.x;
    int c = t * 4;
    const float* bp = (g_deg[n] > 0) ? g_biasP : g_biasN;
    float4 v = make_float4(0.f, 0.f, 0.f, 0.f);
    if (t < 50) {
        float4 ir = *(const float4*)(g_gi + n * 600 + c);
        float4 iz = *(const float4*)(g_gi + n * 600 + 200 + c);
        float4 in_ = *(const float4*)(g_gi + n * 600 + 400 + c);
        float4 hr = *(const float4*)(g_gh + n * 600 + c);
        float4 hz = *(const float4*)(g_gh + n * 600 + 200 + c);
        float4 hn = *(const float4*)(g_gh + n * 600 + 400 + c);
        float4 pv = *(const float4*)(g_prev + n * H + c);
        float4 bp0 = *(const float4*)(bp + c);
        float4 bp1 = *(const float4*)(bp + 200 + c);
        float4 bp2 = *(const float4*)(bp + 400 + c);
        float4 bh0 = *(const float4*)(b_hh + c);
        float4 bh1 = *(const float4*)(b_hh + 200 + c);
        float4 bh2 = *(const float4*)(b_hh + 400 + c);
        float* vv = (float*)&v;
        const float *irp = (const float*)&ir, *izp = (const float*)&iz, *inp = (const float*)&in_;
        const float *hrp = (const float*)&hr, *hzp = (const float*)&hz, *hnp = (const float*)&hn;
        const float *pvp = (const float*)&pv;
        const float *b0p = (const float*)&bp0, *b1p = (const float*)&bp1, *b2p = (const float*)&bp2;
        const float *c0p = (const float*)&bh0, *c1p = (const float*)&bh1, *c2p = (const float*)&bh2;
#pragma unroll
        for (int j = 0; j < 4; j++) {
            float rsum = irp[j] + b0p[j] + hrp[j] + c0p[j];
            float zsum = izp[j] + b1p[j] + hzp[j] + c1p[j];
            float hnv  = hnp[j] + c2p[j];
            float rg = 1.f / (1.f + expf(-rsum));
            float zg = 1.f / (1.f + expf(-zsum));
            float ng = tanhf(inp[j] + b2p[j] + rg * hnv);
            vv[j] = (1.f - zg) * ng + zg * pvp[j];
        }
    }
    float ss = v.x * v.x + v.y * v.y + v.z * v.z + v.w * v.w;
#pragma unroll
    for (int off = 16; off; off >>= 1) ss += __shfl_xor_sync(0xffffffffu, ss, off);
    __shared__ float red[2];
    if ((t & 31) == 0) red[t >> 5] = ss;
    __syncthreads();
    float sc = 1.f / fmaxf(sqrtf(red[0] + red[1]), 1e-12f);
    if (t < 50) *(float4*)(g_prev + n * H + c) = f4scale(v, sc);
}

// ---------------- phase 2: history summaries (vectorized) ----------------
__global__ void __launch_bounds__(64) tmp_kernel(const int* __restrict__ his_idx,
                                                 const int* __restrict__ his_len) {
    int b = blockIdx.x, k = blockIdx.y;
    int t = threadIdx.x;
    int c = t * 4;
    int ln = his_len[b * 3 + k];
    const int* idxp = his_idx + (b * 3 + k) * 32;
    float4 s = make_float4(0.f, 0.f, 0.f, 0.f);
    if (t < 50) {
        int l = 0;
        for (; l + 4 <= ln; l += 4) {
            int a0 = idxp[l], a1 = idxp[l + 1], a2 = idxp[l + 2], a3 = idxp[l + 3];
            float4 v0 = *(const float4*)(g_prev + a0 * H + c);
            float4 v1 = *(const float4*)(g_prev + a1 * H + c);
            float4 v2 = *(const float4*)(g_prev + a2 * H + c);
            float4 v3 = *(const float4*)(g_prev + a3 * H + c);
            s = f4add(f4add(f4add(f4add(s, v0), v1), v2), v3);
        }
        for (; l < ln; l++) s = f4add(s, *(const float4*)(g_prev + idxp[l] * H + c));
    }
    float4 v = f4scale(s, 1.f / fmaxf((float)ln, 1.f));
    float ss = v.x * v.x + v.y * v.y + v.z * v.z + v.w * v.w;
#pragma unroll
    for (int off = 16; off; off >>= 1) ss += __shfl_xor_sync(0xffffffffu, ss, off);
    __shared__ float red[2];
    if ((t & 31) == 0) red[t >> 5] = ss;
    __syncthreads();
    float sc = 1.f / fmaxf(sqrtf(red[0] + red[1]), 1e-12f);
    if (t < 50) *(float4*)(&g_sbuf[k][b * H + c]) = f4scale(v, sc);
}

__global__ void cat_kernel(int k, float timk, const int* __restrict__ data,
                           const int* __restrict__ his_len,
                           const float* __restrict__ af, const float* __restrict__ ap,
                           const float* __restrict__ cf, const float* __restrict__ cp) {
    int b = blockIdx.x, c = threadIdx.x;
    int si = data[b * 4 + 0], ri = data[b * 4 + 1];
    if (c < H) {
        g_cat[b * 648 + c]       = g_prev[si * H + c];
        g_cat[b * 648 + 200 + c] = g_reln[ri * H + c];
        g_cat[b * 648 + 400 + c] = g_sbuf[k][b * H + c];
    }
    if (c < TD) {
        int ln = his_len[b * 3 + k];
        float t = (ln > 0) ? timk : 100.f;
        float v = (c < HDh) ? tanhf((t + 1.f) * af[c] + ap[c])
                            : cosf(t * cf[c - HDh] + cp[c - HDh]);
        g_cat[b * 648 + 600 + c] = v;
    }
}

__global__ void atts_kernel(int k, const float* __restrict__ Wc_w, const float* __restrict__ Wc_b) {
    int warp = (blockIdx.x * blockDim.x + threadIdx.x) >> 5;
    int lane = threadIdx.x & 31;
    if (warp >= NB) return;
    float s = 0.f;
    for (int c = lane; c < H; c += 32) s += g_abuf[warp * H + c] * Wc_w[c];
#pragma unroll
    for (int off = 16; off; off >>= 1) s += __shfl_xor_sync(0xffffffffu, s, off);
    if (lane == 0) g_atts[warp * 3 + k] = s + Wc_b[0];
}

__global__ void combine_kernel(const int* __restrict__ data) {
    int b = blockIdx.x, c = threadIdx.x;
    float a0 = g_atts[b * 3 + 0], a1 = g_atts[b * 3 + 1], a2 = g_atts[b * 3 + 2];
    float m = fmaxf(a0, fmaxf(a1, a2));
    float e0 = expf(a0 - m), e1 = expf(a1 - m), e2 = expf(a2 - m);
    float inv = 1.f / (e0 + e1 + e2);
    if (c < H) {
        int si = data[b * 4 + 0], ri = data[b * 4 + 1];
        float o2 = (e0 * g_sbuf[0][b * H + c] + e1 * g_sbuf[1][b * H + c] +
                    e2 * g_sbuf[2][b * H + c]) * inv;
        g_cat600[b * 600 + c]       = g_prev[si * H + c];
        g_cat600[b * 600 + 200 + c] = g_reln[ri * H + c];
        g_cat600[b * 600 + 400 + c] = o2;
    }
}

// ---------------- host orchestration ----------------
static inline dim3 gemm_grid(int N, int M) { return dim3((N + 63) / 64, (M + 127) / 128); }

extern "C" void kernel_launch(void* const* d_in, const int* in_sizes, int n_in,
                              void* d_out, int out_size) {
    (void)in_sizes; (void)n_in; (void)out_size;
    const int*   src    = (const int*)d_in[0];
    const int*   dst    = (const int*)d_in[1];
    const int*   etype  = (const int*)d_in[2];
    const int*   data   = (const int*)d_in[3];
    const int*   hisidx = (const int*)d_in[4];
    const int*   hislen = (const int*)d_in[5];
    const float* ent    = (const float*)d_in[6];
    const float* loopw  = (const float*)d_in[7];
    const float* rel    = (const float*)d_in[8];
    const float* absf   = (const float*)d_in[9];
    const float* absp   = (const float*)d_in[10];
    const float* cosfr  = (const float*)d_in[11];
    const float* cosph  = (const float*)d_in[12];
    const float* Wn     = (const float*)d_in[13];
    const float* Wsm    = (const float*)d_in[14];
    const float* W_ih   = (const float*)d_in[15];
    const float* W_hh   = (const float*)d_in[16];
    const float* b_ih   = (const float*)d_in[17];
    const float* b_hh   = (const float*)d_in[18];
    const float* Wb_w   = (const float*)d_in[19];
    const float* Wb_b   = (const float*)d_in[20];
    const float* Wc_w   = (const float*)d_in[21];
    const float* Wc_b   = (const float*)d_in[22];
    const float* Wd_w   = (const float*)d_in[23];
    const float* Wd_b   = (const float*)d_in[24];
    float* outp = (float*)d_out;

    float *prev, *hA, *hB, *pre, *gi, *gh, *reln, *cat, *cat600, *abuf, *qb, *WT;
    int* degp;
    void* p;
    cudaGetSymbolAddress(&p, g_prev);   prev   = (float*)p;
    cudaGetSymbolAddress(&p, g_hA);     hA     = (float*)p;
    cudaGetSymbolAddress(&p, g_hB);     hB     = (float*)p;
    cudaGetSymbolAddress(&p, g_pre);    pre    = (float*)p;
    cudaGetSymbolAddress(&p, g_gi);     gi     = (float*)p;
    cudaGetSymbolAddress(&p, g_gh);     gh     = (float*)p;
    cudaGetSymbolAddress(&p, g_reln);   reln   = (float*)p;
    cudaGetSymbolAddress(&p, g_cat);    cat    = (float*)p;
    cudaGetSymbolAddress(&p, g_cat600); cat600 = (float*)p;
    cudaGetSymbolAddress(&p, g_abuf);   abuf   = (float*)p;
    cudaGetSymbolAddress(&p, g_q);      qb     = (float*)p;
    cudaGetSymbolAddress(&p, g_WT);     WT     = (float*)p;
    cudaGetSymbolAddress(&p, g_deg);    degp   = (int*)p;

    float* loopT = WT;
    float* WnT0  = WT + 1 * H * H;
    float* WnT1  = WT + 2 * H * H;
    float* WsT0  = WT + 3 * H * H;
    float* WsT1  = WT + 4 * H * H;

    const dim3 l2nBlk(32, 8);
    const dim3 trBlk(32, 32), trGrid(7, 7);

    // transpose square weights once per launch
    transpose_kernel<<<trGrid, trBlk>>>(loopw, loopT, H, H);
    transpose_kernel<<<trGrid, trBlk>>>(Wn,          WnT0, H, H);
    transpose_kernel<<<trGrid, trBlk>>>(Wn + H * H,  WnT1, H, H);
    transpose_kernel<<<trGrid, trBlk>>>(Wsm,         WsT0, H, H);
    transpose_kernel<<<trGrid, trBlk>>>(Wsm + H * H, WsT1, H, H);

    // rel_n = l2n(rel)
    l2n_kernel<<<(400 + 7) / 8, l2nBlk>>>(rel, reln, 400);
    // prev = l2n(ent @ loop_weight)
    sgemm_kernel<false, false, false><<<gemm_grid(H, NE), 256>>>(
        ent, H, loopT, H, nullptr, nullptr, nullptr, pre, H, NE, H, H);
    l2n_kernel<<<(NE + 7) / 8, l2nBlk>>>(pre, prev, NE);

    for (int i = 0; i < 3; i++) {
        cudaMemsetAsync(degp, 0, NE * sizeof(int), 0);
        count_kernel<<<(EE + 511) / 512, 512>>>(dst + i * EE);
        scan_kernel<<<1, 1024>>>();
        fill_kernel<<<(EE + 511) / 512, 512>>>(src + i * EE, dst + i * EE, etype + i * EE);
        gather1_kernel<<<NE, 64>>>();
        tebias_kernel<<<3, 256>>>(W_ih, b_ih, absf, absp, cosfr, cosph, (float)(2 - i));
        // layer 0: hB = relu(pre @ Wn[0] + hA @ Ws[0])
        gather2_kernel<<<NE, 64>>>(hA);
        sgemm_kernel<true, true, false><<<gemm_grid(H, NE), 256>>>(
            pre, H, WnT0, H, hA, WsT0, nullptr, hB, H, NE, H, H);
        // layer 1: hA = relu(pre @ Wn[1] + hB @ Ws[1])
        gather2_kernel<<<NE, 64>>>(hB);
        sgemm_kernel<true, true, false><<<gemm_grid(H, NE), 256>>>(
            pre, H, WnT1, H, hB, WsT1, nullptr, hA, H, NE, H, H);
        l2n_kernel<<<(NE + 7) / 8, l2nBlk>>>(hA, hA, NE);
        // GRU gates
        sgemm_kernel<false, false, false><<<gemm_grid(3 * H, NE), 256>>>(
            hA, H, W_ih, 248, nullptr, nullptr, nullptr, gi, 3 * H, NE, 3 * H, H);
        sgemm_kernel<false, false, false><<<gemm_grid(3 * H, NE), 256>>>(
            prev, H, W_hh, H, nullptr, nullptr, nullptr, gh, 3 * H, NE, 3 * H, H);
        gru_kernel<<<NE, 64>>>(b_hh);
    }

    // ---- phase 2: batch attention over histories ----
    tmp_kernel<<<dim3(NB, 3), 64>>>(hisidx, hislen);
    for (int k = 0; k < 3; k++) {
        cat_kernel<<<NB, 256>>>(k, (float)(2 - k), data, hislen, absf, absp, cosfr, cosph);
        sgemm_kernel<false, true, true><<<gemm_grid(H, NB), 256>>>(
            cat, 648, Wb_w, 648, nullptr, nullptr, Wb_b, abuf, H, NB, H, 648);
        atts_kernel<<<64, 256>>>(k, Wc_w, Wc_b);
    }
    combine_kernel<<<NB, 256>>>(data);
    sgemm_kernel<false, true, true><<<gemm_grid(H, NB), 256>>>(
        cat600, 600, Wd_w, 600, nullptr, nullptr, Wd_b, qb, H, NB, H, 600);
    // result = q @ out^T
    sgemm_kernel<false, false, false><<<gemm_grid(NE, NB), 256>>>(
        qb, H, prev, H, nullptr, nullptr, nullptr, outp, NE, NB, NE, H);
}

// round 17
// speedup vs baseline: 3.4302x; 1.0699x over previous
#include <cuda_runtime.h>
#include <math.h>
#include <stdint.h>

// ---------------- problem constants ----------------
constexpr int NE  = 20000;   // NUM_E
constexpr int H   = 200;
constexpr int EE  = 200000;  // E
constexpr int NB  = 512;     // BATCH
constexpr int TD  = 48;
constexpr int HDh = 24;      // TD/2

// ---------------- device scratch (no allocs allowed) ----------------
__device__ float g_prev[NE * H];
__device__ float g_hA[NE * H];
__device__ float g_hB[NE * H];
__device__ float g_pre[NE * H];
__device__ float g_relS[NE * H];
__device__ float g_gi[NE * 3 * H];
__device__ float g_gh[NE * 3 * H];
__device__ float g_reln[400 * H];
__device__ int   g_deg[NE];
__device__ int   g_rowptr[NE + 1];
__device__ int   g_cursor[NE];
__device__ int   g_esrc[EE];
__device__ int   g_erel[EE];
__device__ float g_biasP[3 * H];
__device__ float g_biasN[3 * H];
__device__ float g_sbuf[3][NB * H];
__device__ float g_cat[NB * 648];
__device__ float g_abuf[NB * H];
__device__ float g_atts[NB * 3];
__device__ float g_cat600[NB * 600];
__device__ float g_q[NB * H];
// transposed square weights: [0]=loopw^T, [1..2]=Wn^T, [3..4]=Ws^T
__device__ float g_WT[5 * H * H];

__device__ __forceinline__ float4 f4add(float4 a, float4 b) {
    return make_float4(a.x + b.x, a.y + b.y, a.z + b.z, a.w + b.w);
}
__device__ __forceinline__ float4 f4scale(float4 a, float s) {
    return make_float4(a.x * s, a.y * s, a.z * s, a.w * s);
}

// ---------------- TF32 tensor-core GEMM (mma.sync + cp.async pipeline) ----------------
__device__ __forceinline__ uint32_t to_tf32(float x) {
    uint32_t r;
    asm("cvt.rna.tf32.f32 %0, %1;" : "=r"(r) : "f"(x));
    return r;
}

__device__ __forceinline__ void mma_tf32(float* d, const uint32_t* a, const uint32_t* b) {
    asm volatile(
        "mma.sync.aligned.m16n8k8.row.col.f32.tf32.tf32.f32 "
        "{%0,%1,%2,%3}, {%4,%5,%6,%7}, {%8,%9}, {%0,%1,%2,%3};"
        : "+f"(d[0]), "+f"(d[1]), "+f"(d[2]), "+f"(d[3])
        : "r"(a[0]), "r"(a[1]), "r"(a[2]), "r"(a[3]), "r"(b[0]), "r"(b[1]));
}

__device__ __forceinline__ void cp16(void* smem, const void* g, bool v) {
    uint32_t sa = (uint32_t)__cvta_generic_to_shared(smem);
    int sz = v ? 16 : 0;
    asm volatile("cp.async.cg.shared.global [%0], [%1], 16, %2;"
                 :: "r"(sa), "l"(g), "r"(sz) : "memory");
}
#define CP_COMMIT() asm volatile("cp.async.commit_group;" ::: "memory")
#define CP_WAIT1()  asm volatile("cp.async.wait_group 1;" ::: "memory")

// C[M,N] = A[M,K] @ B^T (+ A2 @ B2^T if DUAL) (+ bias if BIAS), relu if RELU
// A: [M, lda] row-major (K contiguous). B: [N, ldb] row-major (K contiguous).
// Requirements: lda, ldb % 4 == 0; ldc, N even. OOB K/M/N zero-filled.
template <bool DUAL, bool RELU, bool BIAS>
__global__ void __launch_bounds__(256, 2) sgemm_kernel(
    const float* __restrict__ A, int lda,
    const float* __restrict__ B, int ldb,
    const float* __restrict__ A2, const float* __restrict__ B2,
    const float* __restrict__ bias,
    float* __restrict__ C, int ldc, int M, int N, int K) {
    constexpr int BM = 128, BN = 128, BK = 16, ST = 3;
    // [row][16 k] raw f32, 16B-chunk swizzle: chunk' = chunk ^ ((row>>1)&3)
    __shared__ float As[ST][BM][BK];
    __shared__ float Bs[ST][BN][BK];
    const int bm = blockIdx.y * BM;
    const int bn = blockIdx.x * BN;
    const int t  = threadIdx.x;
    const int lane = t & 31, warp = t >> 5;
    const int g = lane >> 2, tig = lane & 3;
    const int m0w = (warp & 1) * 64;    // 2 m-warps x 64 rows
    const int n0w = (warp >> 1) * 32;   // 4 n-warps x 32 cols

    const int ksteps = (K + BK - 1) / BK;
    const int nsteps = (DUAL ? 2 : 1) * ksteps;

    float acc[4][4][4] = {};

    const int chunk = t & 3;       // staging chunk (4 k each)
    const int srow  = t >> 2;      // staging row base (0..63)

    auto issue = [&](int s) {
        if (s >= nsteps) return;
        int pass = DUAL ? (s >= ksteps ? 1 : 0) : 0;
        int k0 = (s - pass * ksteps) * BK;
        const float* Ap = pass ? A2 : A;
        const float* Bp = pass ? B2 : B;
        int buf = s % ST;
        int gk = k0 + chunk * 4;
        bool kok = gk < K;
#pragma unroll
        for (int r = 0; r < 2; r++) {
            int m = srow + r * 64;
            int gm = bm + m;
            float* dst = &As[buf][m][(chunk ^ ((m >> 1) & 3)) << 2];
            cp16(dst, Ap + (size_t)gm * lda + gk, (gm < M) && kok);
        }
#pragma unroll
        for (int r = 0; r < 2; r++) {
            int n = srow + r * 64;
            int gn = bn + n;
            float* dst = &Bs[buf][n][(chunk ^ ((n >> 1) & 3)) << 2];
            cp16(dst, Bp + (size_t)gn * ldb + gk, (gn < N) && kok);
        }
    };

    auto compute_sub = [&](int buf, int sub) {
        const int c1 = 2 * sub, c2 = 2 * sub + 1;
        uint32_t a[4][4];
#pragma unroll
        for (int mt = 0; mt < 4; mt++) {
            int mb = m0w + mt * 16 + g;
            int sw = (mb >> 1) & 3;     // same for mb and mb+8
            a[mt][0] = to_tf32(As[buf][mb    ][((c1 ^ sw) << 2) | tig]);
            a[mt][1] = to_tf32(As[buf][mb + 8][((c1 ^ sw) << 2) | tig]);
            a[mt][2] = to_tf32(As[buf][mb    ][((c2 ^ sw) << 2) | tig]);
            a[mt][3] = to_tf32(As[buf][mb + 8][((c2 ^ sw) << 2) | tig]);
        }
        uint32_t b[4][2];
#pragma unroll
        for (int nt = 0; nt < 4; nt++) {
            int nb = n0w + nt * 8 + g;
            int sw = (nb >> 1) & 3;
            b[nt][0] = to_tf32(Bs[buf][nb][((c1 ^ sw) << 2) | tig]);
            b[nt][1] = to_tf32(Bs[buf][nb][((c2 ^ sw) << 2) | tig]);
        }
#pragma unroll
        for (int mt = 0; mt < 4; mt++)
#pragma unroll
            for (int nt = 0; nt < 4; nt++)
                mma_tf32(acc[mt][nt], a[mt], b[nt]);
    };

    issue(0); CP_COMMIT();
    issue(1); CP_COMMIT();
    int s = 0;
#pragma unroll 1
    for (; s + 3 <= nsteps; s += 3) {
        CP_WAIT1();
        __syncthreads();
        issue(s + 2); CP_COMMIT();
        compute_sub(0, 0); compute_sub(0, 1);
        CP_WAIT1();
        __syncthreads();
        issue(s + 3); CP_COMMIT();
        compute_sub(1, 0); compute_sub(1, 1);
        CP_WAIT1();
        __syncthreads();
        issue(s + 4); CP_COMMIT();
        compute_sub(2, 0); compute_sub(2, 1);
    }
#pragma unroll 1
    for (; s < nsteps; s++) {
        CP_WAIT1();
        __syncthreads();
        issue(s + 2); CP_COMMIT();
        int buf = s % ST;
        compute_sub(buf, 0);
        compute_sub(buf, 1);
    }

#pragma unroll
    for (int mt = 0; mt < 4; mt++) {
#pragma unroll
        for (int nt = 0; nt < 4; nt++) {
            int gm = bm + m0w + mt * 16 + g;
            int gn = bn + n0w + nt * 8 + 2 * tig;
            if (gn >= N) continue;
            float b0 = 0.f, b1 = 0.f;
            if (BIAS) { b0 = bias[gn]; b1 = bias[gn + 1]; }
            float v0 = acc[mt][nt][0] + b0, v1 = acc[mt][nt][1] + b1;
            float v2 = acc[mt][nt][2] + b0, v3 = acc[mt][nt][3] + b1;
            if (RELU) {
                v0 = fmaxf(v0, 0.f); v1 = fmaxf(v1, 0.f);
                v2 = fmaxf(v2, 0.f); v3 = fmaxf(v3, 0.f);
            }
            if (gm < M)     *(float2*)(C + (size_t)gm * ldc + gn)       = make_float2(v0, v1);
            if (gm + 8 < M) *(float2*)(C + (size_t)(gm + 8) * ldc + gn) = make_float2(v2, v3);
        }
    }
}

// ---------------- transpose (for square weight matrices) ----------------
__global__ void transpose_kernel(const float* __restrict__ in, float* __restrict__ outp,
                                 int rows, int cols) {
    __shared__ float tile[32][33];
    int x = blockIdx.x * 32 + threadIdx.x;
    int y = blockIdx.y * 32 + threadIdx.y;
    if (x < cols && y < rows) tile[threadIdx.y][threadIdx.x] = in[y * cols + x];
    __syncthreads();
    int ox = blockIdx.y * 32 + threadIdx.x;   // new col = old row
    int oy = blockIdx.x * 32 + threadIdx.y;   // new row = old col
    if (ox < rows && oy < cols) outp[oy * rows + ox] = tile[threadIdx.x][threadIdx.y];
}

// ---------------- row L2 normalize (warp per row) ----------------
__global__ void l2n_kernel(const float* __restrict__ in, float* __restrict__ outp, int rows) {
    int r = blockIdx.x * blockDim.y + threadIdx.y;
    if (r >= rows) return;
    int lane = threadIdx.x;
    float s = 0.f;
    for (int c = lane; c < H; c += 32) { float v = in[r * H + c]; s += v * v; }
#pragma unroll
    for (int off = 16; off; off >>= 1) s += __shfl_xor_sync(0xffffffffu, s, off);
    float sc = 1.f / fmaxf(sqrtf(s), 1e-12f);
    for (int c = lane; c < H; c += 32) outp[r * H + c] = in[r * H + c] * sc;
}

// ---------------- CSR build ----------------
__global__ void count_kernel(const int* __restrict__ dsti) {
    int e = blockIdx.x * blockDim.x + threadIdx.x;
    if (e < EE) atomicAdd(&g_deg[dsti[e]], 1);
}

__global__ void scan_kernel() {
    __shared__ int s[1024];
    int t = threadIdx.x;
    int start = t * 20;
    int end = min(start + 20, NE);
    int local = 0;
    for (int i = start; i < end; i++) local += g_deg[i];
    s[t] = local;
    __syncthreads();
    for (int off = 1; off < 1024; off <<= 1) {
        int v = (t >= off) ? s[t - off] : 0;
        __syncthreads();
        s[t] += v;
        __syncthreads();
    }
    int run = s[t] - local;
    for (int i = start; i < end; i++) {
        g_rowptr[i] = run;
        g_cursor[i] = run;
        run += g_deg[i];
    }
    if (t == 1023) g_rowptr[NE] = run;
}

__global__ void fill_kernel(const int* __restrict__ srci, const int* __restrict__ dsti,
                            const int* __restrict__ eti) {
    int e = blockIdx.x * blockDim.x + threadIdx.x;
    if (e < EE) {
        int p = atomicAdd(&g_cursor[dsti[e]], 1);
        g_esrc[p] = srci[e];
        g_erel[p] = eti[e];
    }
}

// ---------------- vectorized CSR gathers ----------------
__global__ void __launch_bounds__(64) gather1_kernel() {
    int n = blockIdx.x;
    int t = threadIdx.x;
    int b0 = g_rowptr[n], e0 = g_rowptr[n + 1];
    int c = t * 4;
    float4 s1 = make_float4(0.f, 0.f, 0.f, 0.f);
    float4 s2 = make_float4(0.f, 0.f, 0.f, 0.f);
    if (t < 50) {
        int i = b0;
        for (; i + 4 <= e0; i += 4) {
            int a0 = g_esrc[i], a1 = g_esrc[i + 1], a2 = g_esrc[i + 2], a3 = g_esrc[i + 3];
            int r0 = g_erel[i], r1 = g_erel[i + 1], r2 = g_erel[i + 2], r3 = g_erel[i + 3];
            float4 v0 = *(const float4*)(g_prev + a0 * H + c);
            float4 v1 = *(const float4*)(g_prev + a1 * H + c);
            float4 v2 = *(const float4*)(g_prev + a2 * H + c);
            float4 v3 = *(const float4*)(g_prev + a3 * H + c);
            float4 w0 = *(const float4*)(g_reln + r0 * H + c);
            float4 w1 = *(const float4*)(g_reln + r1 * H + c);
            float4 w2 = *(const float4*)(g_reln + r2 * H + c);
            float4 w3 = *(const float4*)(g_reln + r3 * H + c);
            s1 = f4add(f4add(f4add(f4add(s1, v0), v1), v2), v3);
            s2 = f4add(f4add(f4add(f4add(s2, w0), w1), w2), w3);
        }
        for (; i < e0; i++) {
            s1 = f4add(s1, *(const float4*)(g_prev + g_esrc[i] * H + c));
            s2 = f4add(s2, *(const float4*)(g_reln + g_erel[i] * H + c));
        }
    }
    float inv = 1.f / fmaxf((float)(e0 - b0), 1.f);
    float4 v = f4scale(s1, inv);
    float ss = v.x * v.x + v.y * v.y + v.z * v.z + v.w * v.w;
#pragma unroll
    for (int off = 16; off; off >>= 1) ss += __shfl_xor_sync(0xffffffffu, ss, off);
    __shared__ float red[2];
    if ((t & 31) == 0) red[t >> 5] = ss;
    __syncthreads();
    float sc = 1.f / fmaxf(sqrtf(red[0] + red[1]), 1e-12f);
    if (t < 50) {
        *(float4*)(g_hA + n * H + c) = f4scale(v, sc);
        *(float4*)(g_relS + n * H + c) = s2;
    }
}

__global__ void __launch_bounds__(64) gather2_kernel(const float* __restrict__ hsrc) {
    int n = blockIdx.x;
    int t = threadIdx.x;
    if (t >= 50) return;
    int c = t * 4;
    int b0 = g_rowptr[n], e0 = g_rowptr[n + 1];
    float4 s = make_float4(0.f, 0.f, 0.f, 0.f);
    int i = b0;
    for (; i + 4 <= e0; i += 4) {
        int a0 = g_esrc[i], a1 = g_esrc[i + 1], a2 = g_esrc[i + 2], a3 = g_esrc[i + 3];
        float4 v0 = *(const float4*)(hsrc + a0 * H + c);
        float4 v1 = *(const float4*)(hsrc + a1 * H + c);
        float4 v2 = *(const float4*)(hsrc + a2 * H + c);
        float4 v3 = *(const float4*)(hsrc + a3 * H + c);
        s = f4add(f4add(f4add(f4add(s, v0), v1), v2), v3);
    }
    for (; i < e0; i++) s = f4add(s, *(const float4*)(hsrc + g_esrc[i] * H + c));
    float inv = 1.f / fmaxf((float)(e0 - b0), 1.f);
    float4 r = *(const float4*)(g_relS + n * H + c);
    *(float4*)(g_pre + n * H + c) = f4scale(f4add(s, r), inv);
}

// ---------------- time-encoding bias ----------------
__global__ void tebias_kernel(const float* __restrict__ W_ih, const float* __restrict__ b_ih,
                              const float* __restrict__ af, const float* __restrict__ ap,
                              const float* __restrict__ cf, const float* __restrict__ cp,
                              float tpos) {
    int j = blockIdx.x * blockDim.x + threadIdx.x;
    if (j >= 3 * H) return;
    float sp = b_ih[j], sn = b_ih[j];
    for (int d = 0; d < TD; d++) {
        float tep, ten;
        if (d < HDh) {
            tep = tanhf((tpos + 1.f) * af[d] + ap[d]);
            ten = tanhf(101.f * af[d] + ap[d]);
        } else {
            tep = cosf(tpos * cf[d - HDh] + cp[d - HDh]);
            ten = cosf(100.f * cf[d - HDh] + cp[d - HDh]);
        }
        float w = W_ih[j * 248 + 200 + d];
        sp += w * tep;
        sn += w * ten;
    }
    g_biasP[j] = sp;
    g_biasN[j] = sn;
}

// ---------------- GRU update + l2n (vectorized, 64 threads/node) ----------------
__global__ void __launch_bounds__(64) gru_kernel(const float* __restrict__ b_hh) {
    int n = blockIdx.x;
    int t = threadIdx.x;
    int c = t * 4;
    const float* bp = (g_deg[n] > 0) ? g_biasP : g_biasN;
    float4 v = make_float4(0.f, 0.f, 0.f, 0.f);
    if (t < 50) {
        float4 ir = *(const float4*)(g_gi + n * 600 + c);
        float4 iz = *(const float4*)(g_gi + n * 600 + 200 + c);
        float4 in_ = *(const float4*)(g_gi + n * 600 + 400 + c);
        float4 hr = *(const float4*)(g_gh + n * 600 + c);
        float4 hz = *(const float4*)(g_gh + n * 600 + 200 + c);
        float4 hn = *(const float4*)(g_gh + n * 600 + 400 + c);
        float4 pv = *(const float4*)(g_prev + n * H + c);
        float4 bp0 = *(const float4*)(bp + c);
        float4 bp1 = *(const float4*)(bp + 200 + c);
        float4 bp2 = *(const float4*)(bp + 400 + c);
        float4 bh0 = *(const float4*)(b_hh + c);
        float4 bh1 = *(const float4*)(b_hh + 200 + c);
        float4 bh2 = *(const float4*)(b_hh + 400 + c);
        float* vv = (float*)&v;
        const float *irp = (const float*)&ir, *izp = (const float*)&iz, *inp = (const float*)&in_;
        const float *hrp = (const float*)&hr, *hzp = (const float*)&hz, *hnp = (const float*)&hn;
        const float *pvp = (const float*)&pv;
        const float *b0p = (const float*)&bp0, *b1p = (const float*)&bp1, *b2p = (const float*)&bp2;
        const float *c0p = (const float*)&bh0, *c1p = (const float*)&bh1, *c2p = (const float*)&bh2;
#pragma unroll
        for (int j = 0; j < 4; j++) {
            float rsum = irp[j] + b0p[j] + hrp[j] + c0p[j];
            float zsum = izp[j] + b1p[j] + hzp[j] + c1p[j];
            float hnv  = hnp[j] + c2p[j];
            float rg = 1.f / (1.f + expf(-rsum));
            float zg = 1.f / (1.f + expf(-zsum));
            float ng = tanhf(inp[j] + b2p[j] + rg * hnv);
            vv[j] = (1.f - zg) * ng + zg * pvp[j];
        }
    }
    float ss = v.x * v.x + v.y * v.y + v.z * v.z + v.w * v.w;
#pragma unroll
    for (int off = 16; off; off >>= 1) ss += __shfl_xor_sync(0xffffffffu, ss, off);
    __shared__ float red[2];
    if ((t & 31) == 0) red[t >> 5] = ss;
    __syncthreads();
    float sc = 1.f / fmaxf(sqrtf(red[0] + red[1]), 1e-12f);
    if (t < 50) *(float4*)(g_prev + n * H + c) = f4scale(v, sc);
}

// ---------------- phase 2: history summaries (vectorized) ----------------
__global__ void __launch_bounds__(64) tmp_kernel(const int* __restrict__ his_idx,
                                                 const int* __restrict__ his_len) {
    int b = blockIdx.x, k = blockIdx.y;
    int t = threadIdx.x;
    int c = t * 4;
    int ln = his_len[b * 3 + k];
    const int* idxp = his_idx + (b * 3 + k) * 32;
    float4 s = make_float4(0.f, 0.f, 0.f, 0.f);
    if (t < 50) {
        int l = 0;
        for (; l + 4 <= ln; l += 4) {
            int a0 = idxp[l], a1 = idxp[l + 1], a2 = idxp[l + 2], a3 = idxp[l + 3];
            float4 v0 = *(const float4*)(g_prev + a0 * H + c);
            float4 v1 = *(const float4*)(g_prev + a1 * H + c);
            float4 v2 = *(const float4*)(g_prev + a2 * H + c);
            float4 v3 = *(const float4*)(g_prev + a3 * H + c);
            s = f4add(f4add(f4add(f4add(s, v0), v1), v2), v3);
        }
        for (; l < ln; l++) s = f4add(s, *(const float4*)(g_prev + idxp[l] * H + c));
    }
    float4 v = f4scale(s, 1.f / fmaxf((float)ln, 1.f));
    float ss = v.x * v.x + v.y * v.y + v.z * v.z + v.w * v.w;
#pragma unroll
    for (int off = 16; off; off >>= 1) ss += __shfl_xor_sync(0xffffffffu, ss, off);
    __shared__ float red[2];
    if ((t & 31) == 0) red[t >> 5] = ss;
    __syncthreads();
    float sc = 1.f / fmaxf(sqrtf(red[0] + red[1]), 1e-12f);
    if (t < 50) *(float4*)(&g_sbuf[k][b * H + c]) = f4scale(v, sc);
}

__global__ void cat_kernel(int k, float timk, const int* __restrict__ data,
                           const int* __restrict__ his_len,
                           const float* __restrict__ af, const float* __restrict__ ap,
                           const float* __restrict__ cf, const float* __restrict__ cp) {
    int b = blockIdx.x, c = threadIdx.x;
    int si = data[b * 4 + 0], ri = data[b * 4 + 1];
    if (c < H) {
        g_cat[b * 648 + c]       = g_prev[si * H + c];
        g_cat[b * 648 + 200 + c] = g_reln[ri * H + c];
        g_cat[b * 648 + 400 + c] = g_sbuf[k][b * H + c];
    }
    if (c < TD) {
        int ln = his_len[b * 3 + k];
        float t = (ln > 0) ? timk : 100.f;
        float v = (c < HDh) ? tanhf((t + 1.f) * af[c] + ap[c])
                            : cosf(t * cf[c - HDh] + cp[c - HDh]);
        g_cat[b * 648 + 600 + c] = v;
    }
}

__global__ void atts_kernel(int k, const float* __restrict__ Wc_w, const float* __restrict__ Wc_b) {
    int warp = (blockIdx.x * blockDim.x + threadIdx.x) >> 5;
    int lane = threadIdx.x & 31;
    if (warp >= NB) return;
    float s = 0.f;
    for (int c = lane; c < H; c += 32) s += g_abuf[warp * H + c] * Wc_w[c];
#pragma unroll
    for (int off = 16; off; off >>= 1) s += __shfl_xor_sync(0xffffffffu, s, off);
    if (lane == 0) g_atts[warp * 3 + k] = s + Wc_b[0];
}

__global__ void combine_kernel(const int* __restrict__ data) {
    int b = blockIdx.x, c = threadIdx.x;
    float a0 = g_atts[b * 3 + 0], a1 = g_atts[b * 3 + 1], a2 = g_atts[b * 3 + 2];
    float m = fmaxf(a0, fmaxf(a1, a2));
    float e0 = expf(a0 - m), e1 = expf(a1 - m), e2 = expf(a2 - m);
    float inv = 1.f / (e0 + e1 + e2);
    if (c < H) {
        int si = data[b * 4 + 0], ri = data[b * 4 + 1];
        float o2 = (e0 * g_sbuf[0][b * H + c] + e1 * g_sbuf[1][b * H + c] +
                    e2 * g_sbuf[2][b * H + c]) * inv;
        g_cat600[b * 600 + c]       = g_prev[si * H + c];
        g_cat600[b * 600 + 200 + c] = g_reln[ri * H + c];
        g_cat600[b * 600 + 400 + c] = o2;
    }
}

// ---------------- host orchestration ----------------
static inline dim3 gemm_grid(int N, int M) { return dim3((N + 127) / 128, (M + 127) / 128); }

extern "C" void kernel_launch(void* const* d_in, const int* in_sizes, int n_in,
                              void* d_out, int out_size) {
    (void)in_sizes; (void)n_in; (void)out_size;
    const int*   src    = (const int*)d_in[0];
    const int*   dst    = (const int*)d_in[1];
    const int*   etype  = (const int*)d_in[2];
    const int*   data   = (const int*)d_in[3];
    const int*   hisidx = (const int*)d_in[4];
    const int*   hislen = (const int*)d_in[5];
    const float* ent    = (const float*)d_in[6];
    const float* loopw  = (const float*)d_in[7];
    const float* rel    = (const float*)d_in[8];
    const float* absf   = (const float*)d_in[9];
    const float* absp   = (const float*)d_in[10];
    const float* cosfr  = (const float*)d_in[11];
    const float* cosph  = (const float*)d_in[12];
    const float* Wn     = (const float*)d_in[13];
    const float* Wsm    = (const float*)d_in[14];
    const float* W_ih   = (const float*)d_in[15];
    const float* W_hh   = (const float*)d_in[16];
    const float* b_ih   = (const float*)d_in[17];
    const float* b_hh   = (const float*)d_in[18];
    const float* Wb_w   = (const float*)d_in[19];
    const float* Wb_b   = (const float*)d_in[20];
    const float* Wc_w   = (const float*)d_in[21];
    const float* Wc_b   = (const float*)d_in[22];
    const float* Wd_w   = (const float*)d_in[23];
    const float* Wd_b   = (const float*)d_in[24];
    float* outp = (float*)d_out;

    float *prev, *hA, *hB, *pre, *gi, *gh, *reln, *cat, *cat600, *abuf, *qb, *WT;
    int* degp;
    void* p;
    cudaGetSymbolAddress(&p, g_prev);   prev   = (float*)p;
    cudaGetSymbolAddress(&p, g_hA);     hA     = (float*)p;
    cudaGetSymbolAddress(&p, g_hB);     hB     = (float*)p;
    cudaGetSymbolAddress(&p, g_pre);    pre    = (float*)p;
    cudaGetSymbolAddress(&p, g_gi);     gi     = (float*)p;
    cudaGetSymbolAddress(&p, g_gh);     gh     = (float*)p;
    cudaGetSymbolAddress(&p, g_reln);   reln   = (float*)p;
    cudaGetSymbolAddress(&p, g_cat);    cat    = (float*)p;
    cudaGetSymbolAddress(&p, g_cat600); cat600 = (float*)p;
    cudaGetSymbolAddress(&p, g_abuf);   abuf   = (float*)p;
    cudaGetSymbolAddress(&p, g_q);      qb     = (float*)p;
    cudaGetSymbolAddress(&p, g_WT);     WT     = (float*)p;
    cudaGetSymbolAddress(&p, g_deg);    degp   = (int*)p;

    float* loopT = WT;
    float* WnT0  = WT + 1 * H * H;
    float* WnT1  = WT + 2 * H * H;
    float* WsT0  = WT + 3 * H * H;
    float* WsT1  = WT + 4 * H * H;

    const dim3 l2nBlk(32, 8);
    const dim3 trBlk(32, 32), trGrid(7, 7);

    // transpose square weights once per launch
    transpose_kernel<<<trGrid, trBlk>>>(loopw, loopT, H, H);
    transpose_kernel<<<trGrid, trBlk>>>(Wn,          WnT0, H, H);
    transpose_kernel<<<trGrid, trBlk>>>(Wn + H * H,  WnT1, H, H);
    transpose_kernel<<<trGrid, trBlk>>>(Wsm,         WsT0, H, H);
    transpose_kernel<<<trGrid, trBlk>>>(Wsm + H * H, WsT1, H, H);

    // rel_n = l2n(rel)
    l2n_kernel<<<(400 + 7) / 8, l2nBlk>>>(rel, reln, 400);
    // prev = l2n(ent @ loop_weight)
    sgemm_kernel<false, false, false><<<gemm_grid(H, NE), 256>>>(
        ent, H, loopT, H, nullptr, nullptr, nullptr, pre, H, NE, H, H);
    l2n_kernel<<<(NE + 7) / 8, l2nBlk>>>(pre, prev, NE);

    for (int i = 0; i < 3; i++) {
        cudaMemsetAsync(degp, 0, NE * sizeof(int), 0);
        count_kernel<<<(EE + 511) / 512, 512>>>(dst + i * EE);
        scan_kernel<<<1, 1024>>>();
        fill_kernel<<<(EE + 511) / 512, 512>>>(src + i * EE, dst + i * EE, etype + i * EE);
        gather1_kernel<<<NE, 64>>>();
        tebias_kernel<<<3, 256>>>(W_ih, b_ih, absf, absp, cosfr, cosph, (float)(2 - i));
        // layer 0: hB = relu(pre @ Wn[0] + hA @ Ws[0])
        gather2_kernel<<<NE, 64>>>(hA);
        sgemm_kernel<true, true, false><<<gemm_grid(H, NE), 256>>>(
            pre, H, WnT0, H, hA, WsT0, nullptr, hB, H, NE, H, H);
        // layer 1: hA = relu(pre @ Wn[1] + hB @ Ws[1])
        gather2_kernel<<<NE, 64>>>(hB);
        sgemm_kernel<true, true, false><<<gemm_grid(H, NE), 256>>>(
            pre, H, WnT1, H, hB, WsT1, nullptr, hA, H, NE, H, H);
        l2n_kernel<<<(NE + 7) / 8, l2nBlk>>>(hA, hA, NE);
        // GRU gates
        sgemm_kernel<false, false, false><<<gemm_grid(3 * H, NE), 256>>>(
            hA, H, W_ih, 248, nullptr, nullptr, nullptr, gi, 3 * H, NE, 3 * H, H);
        sgemm_kernel<false, false, false><<<gemm_grid(3 * H, NE), 256>>>(
            prev, H, W_hh, H, nullptr, nullptr, nullptr, gh, 3 * H, NE, 3 * H, H);
        gru_kernel<<<NE, 64>>>(b_hh);
    }

    // ---- phase 2: batch attention over histories ----
    tmp_kernel<<<dim3(NB, 3), 64>>>(hisidx, hislen);
    for (int k = 0; k < 3; k++) {
        cat_kernel<<<NB, 256>>>(k, (float)(2 - k), data, hislen, absf, absp, cosfr, cosph);
        sgemm_kernel<false, true, true><<<gemm_grid(H, NB), 256>>>(
            cat, 648, Wb_w, 648, nullptr, nullptr, Wb_b, abuf, H, NB, H, 648);
        atts_kernel<<<64, 256>>>(k, Wc_w, Wc_b);
    }
    combine_kernel<<<NB, 256>>>(data);
    sgemm_kernel<false, true, true><<<gemm_grid(H, NB), 256>>>(
        cat600, 600, Wd_w, 600, nullptr, nullptr, Wd_b, qb, H, NB, H, 600);
    // result = q @ out^T
    sgemm_kernel<false, false, false><<<gemm_grid(NE, NB), 256>>>(
        qb, H, prev, H, nullptr, nullptr, nullptr, outp, NE, NB, NE, H);
}